// round 4
// baseline (speedup 1.0000x reference)
#include <cuda_runtime.h>
#include <math.h>

// Shapes
#define BB   4
#define HH   256
#define WWI  256
#define DIMI 96
#define DOUT 192
#define HID  768
#define HP   128
#define WP   128
#define RS   193   // padded row stride for k/v/q smem buffers (kills bank conflicts)

// Scratch (allowed: __device__ globals, no runtime allocation)
__device__ float g_xn[(size_t)BB * HH * WWI * DIMI];   // LN1 output, ~100.7 MB
__device__ float g_y [(size_t)BB * HP * WP * DOUT];    // shortcut + attn out, ~50.3 MB

// ---------------------------------------------------------------------------
// K1: LayerNorm over DIM=96, one warp per token
// ---------------------------------------------------------------------------
__global__ __launch_bounds__(256) void k_ln1(const float* __restrict__ x,
                                             const float* __restrict__ gma,
                                             const float* __restrict__ bta) {
    int wid  = blockIdx.x * (blockDim.x >> 5) + (threadIdx.x >> 5);
    int lane = threadIdx.x & 31;
    const float* xp = x + (size_t)wid * 96;
    float v0 = xp[lane], v1 = xp[lane + 32], v2 = xp[lane + 64];
    float s = v0 + v1 + v2;
#pragma unroll
    for (int o = 16; o; o >>= 1) s += __shfl_xor_sync(0xffffffffu, s, o);
    float m = s * (1.0f / 96.0f);
    float d0 = v0 - m, d1 = v1 - m, d2 = v2 - m;
    float q = d0 * d0 + d1 * d1 + d2 * d2;
#pragma unroll
    for (int o = 16; o; o >>= 1) q += __shfl_xor_sync(0xffffffffu, q, o);
    float inv = rsqrtf(q * (1.0f / 96.0f) + 1e-6f);
    float* op = g_xn + (size_t)wid * 96;
    op[lane]      = d0 * inv * gma[lane]      + bta[lane];
    op[lane + 32] = d1 * inv * gma[lane + 32] + bta[lane + 32];
    op[lane + 64] = d2 * inv * gma[lane + 64] + bta[lane + 64];
}

// ---------------------------------------------------------------------------
// K2: shortcut = maxpool2x2(xn @ proj_w + proj_b)
// block = 384 threads; covers 8 pooled pixels of one pooled row (32 input tokens)
// ---------------------------------------------------------------------------
__global__ __launch_bounds__(384) void k_short(const float* __restrict__ pw,
                                               const float* __restrict__ pb) {
    __shared__ float sx[32 * 96];    // 12 KB
    __shared__ float pr[32 * 192];   // 24 KB
    int blk = blockIdx.x;
    int pwg = blk & 15, ph = (blk >> 4) & 127, b = blk >> 11;
    int tid = threadIdx.x;

    for (int i = tid; i < 32 * 24; i += 384) {   // float4 granularity
        int t = i / 24, kq = i - t * 24;
        int gr = 2 * ph + (t >> 4);
        int gc = (pwg << 4) + (t & 15);
        ((float4*)sx)[i] =
            *(const float4*)(g_xn + (((size_t)b * 256 + gr) * 256 + gc) * 96 + kq * 4);
    }
    __syncthreads();

    int c = tid % 192, z = tid / 192;
    float acc[16];
#pragma unroll
    for (int t = 0; t < 16; t++) acc[t] = 0.f;
    const float* sxp = sx + z * 16 * 96;
    for (int k0 = 0; k0 < 96; k0 += 4) {
        float w0 = pw[(k0 + 0) * 192 + c], w1 = pw[(k0 + 1) * 192 + c];
        float w2 = pw[(k0 + 2) * 192 + c], w3 = pw[(k0 + 3) * 192 + c];
#pragma unroll
        for (int t = 0; t < 16; t++) {
            float4 xv = *(const float4*)(sxp + t * 96 + k0);
            acc[t] = fmaf(xv.x, w0, acc[t]); acc[t] = fmaf(xv.y, w1, acc[t]);
            acc[t] = fmaf(xv.z, w2, acc[t]); acc[t] = fmaf(xv.w, w3, acc[t]);
        }
    }
    float bb = pb[c];
#pragma unroll
    for (int t = 0; t < 16; t++) pr[(z * 16 + t) * 192 + c] = acc[t] + bb;
    __syncthreads();

    for (int i = tid; i < 8 * 192; i += 384) {
        int p = i / 192, cc = i - p * 192;
        float m = fmaxf(fmaxf(pr[(2 * p) * 192 + cc], pr[(2 * p + 1) * 192 + cc]),
                        fmaxf(pr[(16 + 2 * p) * 192 + cc], pr[(17 + 2 * p) * 192 + cc]));
        g_y[(((size_t)b * 128 + ph) * 128 + (pwg * 8 + p)) * 192 + cc] = m;
    }
}

// ---------------------------------------------------------------------------
// K3: fully-fused window attention.  One 384-thread block per 8x8 window.
// smem (floats): sx[6144] | wst[18432] | kb[64*193] | vb[64*193] | qb[16*193]
// wst region reused for probs[48*65] and outb[16*192] after qkv GEMMs.
// ---------------------------------------------------------------------------
__global__ __launch_bounds__(384) void k_attn(const float* __restrict__ qkvw,
                                              const float* __restrict__ qkvb,
                                              const float* __restrict__ apw,
                                              const float* __restrict__ apb) {
    extern __shared__ float sm[];
    float* sx    = sm;            // 64 x 96
    float* wst   = sm + 6144;     // 96 x 192 staged weights
    float* kb    = sm + 24576;    // 64 x RS
    float* vb    = sm + 36928;    // 64 x RS
    float* qb    = sm + 49280;    // 16 x RS (pooled, pre-scaled)
    float* probs = wst;           // 48 x 65
    float* outb  = wst + 3120;    // 16 x 192 (16B aligned)

    int wj = blockIdx.x & 31, wi = (blockIdx.x >> 5) & 31, b = blockIdx.x >> 10;
    int tid = threadIdx.x;

    // load LN'd window tile (float4: 96 floats = 24 float4 per token)
    for (int i = tid; i < 64 * 24; i += 384) {
        int t = i / 24, kq = i - t * 24;
        int gr = wi * 8 + (t >> 3), gc = wj * 8 + (t & 7);
        ((float4*)sx)[i] =
            *(const float4*)(g_xn + (((size_t)b * 256 + gr) * 256 + gc) * 96 + kq * 4);
    }

    int c = tid % 192, z = tid / 192;

    // qkv GEMMs: part 0 = Q (into kb as temp, then pooled), 1 = K, 2 = V
    for (int part = 0; part < 3; part++) {
        __syncthreads();
        // stage 96x192 weight slab; rows of the 576-wide matrix, part offset 192
        for (int i = tid; i < 96 * 48; i += 384) {    // 48 float4 per row
            int k = i / 48, cq = i - k * 48;
            ((float4*)wst)[k * 48 + cq] =
                *(const float4*)(qkvw + (size_t)k * 576 + part * 192 + cq * 4);
        }
        __syncthreads();
        float bb = qkvb[part * 192 + c];
        float* dst = (part == 2) ? vb : kb;
        for (int tt = 0; tt < 2; tt++) {
            int t0 = (z * 2 + tt) * 16;
            float acc[16];
#pragma unroll
            for (int t = 0; t < 16; t++) acc[t] = bb;
            const float* sxp = sx + t0 * 96;
            for (int k0 = 0; k0 < 96; k0 += 4) {
                float w0 = wst[(k0 + 0) * 192 + c], w1 = wst[(k0 + 1) * 192 + c];
                float w2 = wst[(k0 + 2) * 192 + c], w3 = wst[(k0 + 3) * 192 + c];
#pragma unroll
                for (int t = 0; t < 16; t++) {
                    float4 xv = *(const float4*)(sxp + t * 96 + k0);
                    acc[t] = fmaf(xv.x, w0, acc[t]); acc[t] = fmaf(xv.y, w1, acc[t]);
                    acc[t] = fmaf(xv.z, w2, acc[t]); acc[t] = fmaf(xv.w, w3, acc[t]);
                }
            }
#pragma unroll
            for (int t = 0; t < 16; t++) dst[(t0 + t) * RS + c] = acc[t];
        }
        if (part == 0) {
            __syncthreads();
            // maxpool2x2 of Q within the 8x8 window, pre-apply 1/sqrt(64)
            for (int i = tid; i < 16 * 192; i += 384) {
                int qi = i / 192, cc = i - qi * 192;
                int prw = qi >> 2, pcl = qi & 3;
                int t00 = (2 * prw) * 8 + 2 * pcl;
                float m = fmaxf(fmaxf(kb[t00 * RS + cc], kb[(t00 + 1) * RS + cc]),
                                fmaxf(kb[(t00 + 8) * RS + cc], kb[(t00 + 9) * RS + cc]));
                qb[qi * RS + cc] = m * 0.125f;
            }
        }
    }
    __syncthreads();

    // scores: thread = (z -> qi half, h, ki)
    {
        int hk = tid % 192;
        int ki = hk & 63, h = hk >> 6;
        int q0 = z * 8;
        float acc[8];
#pragma unroll
        for (int i = 0; i < 8; i++) acc[i] = 0.f;
        const float* kpt = kb + ki * RS + h * 64;
        const float* qpt = qb + q0 * RS + h * 64;
        for (int d = 0; d < 64; d++) {
            float kv = kpt[d];
#pragma unroll
            for (int i = 0; i < 8; i++) acc[i] = fmaf(qpt[i * RS + d], kv, acc[i]);
        }
#pragma unroll
        for (int i = 0; i < 8; i++) probs[(h * 16 + q0 + i) * 65 + ki] = acc[i];
    }
    __syncthreads();

    // softmax over ki (48 rows)
    if (tid < 48) {
        float* row = probs + tid * 65;
        float mx = -1e30f;
        for (int i = 0; i < 64; i++) mx = fmaxf(mx, row[i]);
        float s = 0.f;
        for (int i = 0; i < 64; i++) { float e = __expf(row[i] - mx); row[i] = e; s += e; }
        float r = 1.0f / s;
        for (int i = 0; i < 64; i++) row[i] *= r;
    }
    __syncthreads();

    // out = probs @ V
    {
        int j = tid % 192;
        int h = j >> 6;
        int q0 = z * 8;
        float acc[8];
#pragma unroll
        for (int i = 0; i < 8; i++) acc[i] = 0.f;
        for (int ki = 0; ki < 64; ki++) {
            float vv = vb[ki * RS + j];
#pragma unroll
            for (int i = 0; i < 8; i++)
                acc[i] = fmaf(probs[(h * 16 + q0 + i) * 65 + ki], vv, acc[i]);
        }
#pragma unroll
        for (int i = 0; i < 8; i++) outb[(q0 + i) * 192 + j] = acc[i];
    }
    __syncthreads();

    // attn_proj + add shortcut into g_y
    {
        int q0 = z * 8;
        float acc[8];
        float bb = apb[c];
#pragma unroll
        for (int i = 0; i < 8; i++) acc[i] = bb;
        for (int j0 = 0; j0 < 192; j0 += 4) {
            float w0 = apw[(j0 + 0) * 192 + c], w1 = apw[(j0 + 1) * 192 + c];
            float w2 = apw[(j0 + 2) * 192 + c], w3 = apw[(j0 + 3) * 192 + c];
#pragma unroll
            for (int i = 0; i < 8; i++) {
                float4 ov = *(const float4*)(outb + (q0 + i) * 192 + j0);
                acc[i] = fmaf(ov.x, w0, acc[i]); acc[i] = fmaf(ov.y, w1, acc[i]);
                acc[i] = fmaf(ov.z, w2, acc[i]); acc[i] = fmaf(ov.w, w3, acc[i]);
            }
        }
#pragma unroll
        for (int i = 0; i < 8; i++) {
            int qi = q0 + i;
            int gr = wi * 4 + (qi >> 2), gc = wj * 4 + (qi & 3);
            size_t yi = (((size_t)b * 128 + gr) * 128 + gc) * 192 + c;
            g_y[yi] += acc[i];
        }
    }
}

// ---------------------------------------------------------------------------
// K4: LN2 + MLP (gelu exact) + residual.  384 threads, 32 tokens/block.
// smem: syn[32*192] | hbuf[32*768]  = 120 KB
// ---------------------------------------------------------------------------
__global__ __launch_bounds__(384) void k_mlp(const float* __restrict__ g2,
                                             const float* __restrict__ b2,
                                             const float* __restrict__ w1,
                                             const float* __restrict__ b1,
                                             const float* __restrict__ w2,
                                             const float* __restrict__ bo,
                                             float* __restrict__ out) {
    extern __shared__ float sm[];
    float* syn  = sm;          // 32 x 192
    float* hbuf = sm + 6144;   // 32 x 768
    int tid = threadIdx.x;
    int tok0 = blockIdx.x * 32;
    int warp = tid >> 5, lane = tid & 31;

    for (int t = warp; t < 32; t += 12) {
        const float* yp = g_y + (size_t)(tok0 + t) * 192;
        float v[6];
        float s = 0.f;
#pragma unroll
        for (int i = 0; i < 6; i++) { v[i] = yp[lane + 32 * i]; s += v[i]; }
#pragma unroll
        for (int o = 16; o; o >>= 1) s += __shfl_xor_sync(0xffffffffu, s, o);
        float m = s * (1.0f / 192.0f);
        float q = 0.f;
#pragma unroll
        for (int i = 0; i < 6; i++) { v[i] -= m; q += v[i] * v[i]; }
#pragma unroll
        for (int o = 16; o; o >>= 1) q += __shfl_xor_sync(0xffffffffu, q, o);
        float inv = rsqrtf(q * (1.0f / 192.0f) + 1e-6f);
#pragma unroll
        for (int i = 0; i < 6; i++)
            syn[t * 192 + lane + 32 * i] = v[i] * inv * g2[lane + 32 * i] + b2[lane + 32 * i];
    }
    __syncthreads();

    // hidden = gelu(syn @ w1 + b1)
    for (int pass = 0; pass < 2; pass++) {
        int c = tid + pass * 384;
        float acc[32];
#pragma unroll
        for (int t = 0; t < 32; t++) acc[t] = 0.f;
        for (int k0 = 0; k0 < 192; k0 += 4) {
            float w_0 = w1[(k0 + 0) * 768 + c], w_1 = w1[(k0 + 1) * 768 + c];
            float w_2 = w1[(k0 + 2) * 768 + c], w_3 = w1[(k0 + 3) * 768 + c];
#pragma unroll
            for (int t = 0; t < 32; t++) {
                float4 xv = *(const float4*)(syn + t * 192 + k0);
                acc[t] = fmaf(xv.x, w_0, acc[t]); acc[t] = fmaf(xv.y, w_1, acc[t]);
                acc[t] = fmaf(xv.z, w_2, acc[t]); acc[t] = fmaf(xv.w, w_3, acc[t]);
            }
        }
        float bias = b1[c];
#pragma unroll
        for (int t = 0; t < 32; t++) {
            float u = acc[t] + bias;
            hbuf[t * 768 + c] = 0.5f * u * (1.0f + erff(u * 0.70710678118f));
        }
    }
    __syncthreads();

    // out = y + hbuf @ w2 + bo
    {
        int c = tid % 192, z = tid / 192;
        int t0 = z * 16;
        float acc[16];
        float bias = bo[c];
#pragma unroll
        for (int t = 0; t < 16; t++) acc[t] = bias;
        for (int k0 = 0; k0 < 768; k0 += 4) {
            float w_0 = w2[(k0 + 0) * 192 + c], w_1 = w2[(k0 + 1) * 192 + c];
            float w_2 = w2[(k0 + 2) * 192 + c], w_3 = w2[(k0 + 3) * 192 + c];
#pragma unroll
            for (int t = 0; t < 16; t++) {
                float4 hv = *(const float4*)(hbuf + (t0 + t) * 768 + k0);
                acc[t] = fmaf(hv.x, w_0, acc[t]); acc[t] = fmaf(hv.y, w_1, acc[t]);
                acc[t] = fmaf(hv.z, w_2, acc[t]); acc[t] = fmaf(hv.w, w_3, acc[t]);
            }
        }
#pragma unroll
        for (int t = 0; t < 16; t++) {
            size_t idx = (size_t)(tok0 + t0 + t) * 192 + c;
            out[idx] = g_y[idx] + acc[t];
        }
    }
}

// ---------------------------------------------------------------------------
extern "C" void kernel_launch(void* const* d_in, const int* in_sizes, int n_in,
                              void* d_out, int out_size) {
    const float* x    = (const float*)d_in[0];
    const float* n1g  = (const float*)d_in[1];
    const float* n1b  = (const float*)d_in[2];
    const float* pw   = (const float*)d_in[3];
    const float* pb   = (const float*)d_in[4];
    const float* qkvw = (const float*)d_in[5];
    const float* qkvb = (const float*)d_in[6];
    const float* apw  = (const float*)d_in[7];
    const float* apb  = (const float*)d_in[8];
    const float* n2g  = (const float*)d_in[9];
    const float* n2b  = (const float*)d_in[10];
    const float* w1   = (const float*)d_in[11];
    const float* b1   = (const float*)d_in[12];
    const float* w2   = (const float*)d_in[13];
    const float* b2   = (const float*)d_in[14];
    float* out = (float*)d_out;

    cudaFuncSetAttribute(k_attn, cudaFuncAttributeMaxDynamicSharedMemorySize, 209472);
    cudaFuncSetAttribute(k_mlp,  cudaFuncAttributeMaxDynamicSharedMemorySize, 122880);

    k_ln1 <<<32768, 256>>>(x, n1g, n1b);
    k_short<<<8192, 384>>>(pw, pb);
    k_attn <<<4096, 384, 209472>>>(qkvw, qkvb, apw, apb);
    k_mlp  <<<2048, 384, 122880>>>(n2g, n2b, w1, b1, w2, b2, out);
}

// round 5
// speedup vs baseline: 1.1556x; 1.1556x over previous
#include <cuda_runtime.h>
#include <math.h>

// Shapes
#define BB   4
#define HH   256
#define WWI  256
#define DIMI 96
#define DOUT 192
#define HID  768
#define HP   128
#define WP   128
#define RS   193   // padded row stride for k/v/q smem buffers (kills bank conflicts)

// Scratch (allowed: __device__ globals, no runtime allocation)
__device__ float g_xn[(size_t)BB * HH * WWI * DIMI];   // LN1 output, ~100.7 MB
__device__ float g_y [(size_t)BB * HP * WP * DOUT];    // shortcut + attn out, ~50.3 MB

// ---------------------------------------------------------------------------
// K1: LayerNorm over DIM=96, one warp per token
// ---------------------------------------------------------------------------
__global__ __launch_bounds__(256) void k_ln1(const float* __restrict__ x,
                                             const float* __restrict__ gma,
                                             const float* __restrict__ bta) {
    int wid  = blockIdx.x * (blockDim.x >> 5) + (threadIdx.x >> 5);
    int lane = threadIdx.x & 31;
    const float* xp = x + (size_t)wid * 96;
    float v0 = xp[lane], v1 = xp[lane + 32], v2 = xp[lane + 64];
    float s = v0 + v1 + v2;
#pragma unroll
    for (int o = 16; o; o >>= 1) s += __shfl_xor_sync(0xffffffffu, s, o);
    float m = s * (1.0f / 96.0f);
    float d0 = v0 - m, d1 = v1 - m, d2 = v2 - m;
    float q = d0 * d0 + d1 * d1 + d2 * d2;
#pragma unroll
    for (int o = 16; o; o >>= 1) q += __shfl_xor_sync(0xffffffffu, q, o);
    float inv = rsqrtf(q * (1.0f / 96.0f) + 1e-6f);
    float* op = g_xn + (size_t)wid * 96;
    op[lane]      = d0 * inv * gma[lane]      + bta[lane];
    op[lane + 32] = d1 * inv * gma[lane + 32] + bta[lane + 32];
    op[lane + 64] = d2 * inv * gma[lane + 64] + bta[lane + 64];
}

// ---------------------------------------------------------------------------
// K2: shortcut = maxpool2x2(xn @ proj_w + proj_b)
// ---------------------------------------------------------------------------
__global__ __launch_bounds__(384) void k_short(const float* __restrict__ pw,
                                               const float* __restrict__ pb) {
    __shared__ float sx[32 * 96];    // 12 KB
    __shared__ float pr[32 * 192];   // 24 KB
    int blk = blockIdx.x;
    int pwg = blk & 15, ph = (blk >> 4) & 127, b = blk >> 11;
    int tid = threadIdx.x;

    for (int i = tid; i < 32 * 24; i += 384) {   // float4 granularity
        int t = i / 24, kq = i - t * 24;
        int gr = 2 * ph + (t >> 4);
        int gc = (pwg << 4) + (t & 15);
        ((float4*)sx)[i] =
            *(const float4*)(g_xn + (((size_t)b * 256 + gr) * 256 + gc) * 96 + kq * 4);
    }
    __syncthreads();

    int c = tid % 192, z = tid / 192;
    float acc[16];
#pragma unroll
    for (int t = 0; t < 16; t++) acc[t] = 0.f;
    const float* sxp = sx + z * 16 * 96;
    for (int k0 = 0; k0 < 96; k0 += 4) {
        float w0 = pw[(k0 + 0) * 192 + c], w1 = pw[(k0 + 1) * 192 + c];
        float w2 = pw[(k0 + 2) * 192 + c], w3 = pw[(k0 + 3) * 192 + c];
#pragma unroll
        for (int t = 0; t < 16; t++) {
            float4 xv = *(const float4*)(sxp + t * 96 + k0);
            acc[t] = fmaf(xv.x, w0, acc[t]); acc[t] = fmaf(xv.y, w1, acc[t]);
            acc[t] = fmaf(xv.z, w2, acc[t]); acc[t] = fmaf(xv.w, w3, acc[t]);
        }
    }
    float bb = pb[c];
#pragma unroll
    for (int t = 0; t < 16; t++) pr[(z * 16 + t) * 192 + c] = acc[t] + bb;
    __syncthreads();

    for (int i = tid; i < 8 * 192; i += 384) {
        int p = i / 192, cc = i - p * 192;
        float m = fmaxf(fmaxf(pr[(2 * p) * 192 + cc], pr[(2 * p + 1) * 192 + cc]),
                        fmaxf(pr[(16 + 2 * p) * 192 + cc], pr[(17 + 2 * p) * 192 + cc]));
        g_y[(((size_t)b * 128 + ph) * 128 + (pwg * 8 + p)) * 192 + cc] = m;
    }
}

// ---------------------------------------------------------------------------
// K3: fully-fused window attention.  One 768-thread block per 8x8 window.
// smem (floats): sx[6144] | wst[18432] | kb[64*193] | vb[64*193] | qb[16*193]
// wst region reused for probs[48*65] and outb[16*192] after qkv GEMMs.
// ---------------------------------------------------------------------------
__global__ __launch_bounds__(768, 1) void k_attn(const float* __restrict__ qkvw,
                                                 const float* __restrict__ qkvb,
                                                 const float* __restrict__ apw,
                                                 const float* __restrict__ apb) {
    extern __shared__ float sm[];
    float* sx    = sm;            // 64 x 96
    float* wst   = sm + 6144;     // 96 x 192 staged weights
    float* kb    = sm + 24576;    // 64 x RS
    float* vb    = sm + 36928;    // 64 x RS
    float* qb    = sm + 49280;    // 16 x RS (pooled, pre-scaled)
    float* probs = wst;           // 48 x 65
    float* outb  = wst + 3120;    // 16 x 192 (16B aligned)

    int wj = blockIdx.x & 31, wi = (blockIdx.x >> 5) & 31, b = blockIdx.x >> 10;
    int tid = threadIdx.x;

    // load LN'd window tile (float4: 96 floats = 24 float4 per token)
    for (int i = tid; i < 64 * 24; i += 768) {
        int t = i / 24, kq = i - t * 24;
        int gr = wi * 8 + (t >> 3), gc = wj * 8 + (t & 7);
        ((float4*)sx)[i] =
            *(const float4*)(g_xn + (((size_t)b * 256 + gr) * 256 + gc) * 96 + kq * 4);
    }

    int c = tid % 192, z = tid / 192;   // z in 0..3

    // qkv GEMMs: part 0 = Q (into kb as temp, then pooled), 1 = K, 2 = V
    for (int part = 0; part < 3; part++) {
        __syncthreads();
        // stage 96x192 weight slab
        for (int i = tid; i < 96 * 48; i += 768) {    // 48 float4 per row
            int k = i / 48, cq = i - k * 48;
            ((float4*)wst)[k * 48 + cq] =
                *(const float4*)(qkvw + (size_t)k * 576 + part * 192 + cq * 4);
        }
        __syncthreads();
        float bb = qkvb[part * 192 + c];
        float* dst = (part == 2) ? vb : kb;
        {
            int t0 = z * 16;
            float acc[16];
#pragma unroll
            for (int t = 0; t < 16; t++) acc[t] = bb;
            const float* sxp = sx + t0 * 96;
            for (int k0 = 0; k0 < 96; k0 += 4) {
                float w0 = wst[(k0 + 0) * 192 + c], w1 = wst[(k0 + 1) * 192 + c];
                float w2 = wst[(k0 + 2) * 192 + c], w3 = wst[(k0 + 3) * 192 + c];
#pragma unroll
                for (int t = 0; t < 16; t++) {
                    float4 xv = *(const float4*)(sxp + t * 96 + k0);
                    acc[t] = fmaf(xv.x, w0, acc[t]); acc[t] = fmaf(xv.y, w1, acc[t]);
                    acc[t] = fmaf(xv.z, w2, acc[t]); acc[t] = fmaf(xv.w, w3, acc[t]);
                }
            }
#pragma unroll
            for (int t = 0; t < 16; t++) dst[(t0 + t) * RS + c] = acc[t];
        }
        if (part == 0) {
            __syncthreads();
            // maxpool2x2 of Q within the 8x8 window, pre-apply 1/sqrt(64)
            for (int i = tid; i < 16 * 192; i += 768) {
                int qi = i / 192, cc = i - qi * 192;
                int prw = qi >> 2, pcl = qi & 3;
                int t00 = (2 * prw) * 8 + 2 * pcl;
                float m = fmaxf(fmaxf(kb[t00 * RS + cc], kb[(t00 + 1) * RS + cc]),
                                fmaxf(kb[(t00 + 8) * RS + cc], kb[(t00 + 9) * RS + cc]));
                qb[qi * RS + cc] = m * 0.125f;
            }
        }
    }
    __syncthreads();

    // scores: thread = (z -> 4 q rows, h, ki)
    {
        int hk = tid % 192;
        int ki = hk & 63, h = hk >> 6;
        int q0 = z * 4;
        float acc[4];
#pragma unroll
        for (int i = 0; i < 4; i++) acc[i] = 0.f;
        const float* kpt = kb + ki * RS + h * 64;
        const float* qpt = qb + q0 * RS + h * 64;
        for (int d = 0; d < 64; d++) {
            float kv = kpt[d];
#pragma unroll
            for (int i = 0; i < 4; i++) acc[i] = fmaf(qpt[i * RS + d], kv, acc[i]);
        }
#pragma unroll
        for (int i = 0; i < 4; i++) probs[(h * 16 + q0 + i) * 65 + ki] = acc[i];
    }
    __syncthreads();

    // softmax over ki (48 rows)
    if (tid < 48) {
        float* row = probs + tid * 65;
        float mx = -1e30f;
        for (int i = 0; i < 64; i++) mx = fmaxf(mx, row[i]);
        float s = 0.f;
        for (int i = 0; i < 64; i++) { float e = __expf(row[i] - mx); row[i] = e; s += e; }
        float r = 1.0f / s;
        for (int i = 0; i < 64; i++) row[i] *= r;
    }
    __syncthreads();

    // out = probs @ V
    {
        int j = tid % 192;
        int h = j >> 6;
        int q0 = z * 4;
        float acc[4];
#pragma unroll
        for (int i = 0; i < 4; i++) acc[i] = 0.f;
        for (int ki = 0; ki < 64; ki++) {
            float vv = vb[ki * RS + j];
#pragma unroll
            for (int i = 0; i < 4; i++)
                acc[i] = fmaf(probs[(h * 16 + q0 + i) * 65 + ki], vv, acc[i]);
        }
#pragma unroll
        for (int i = 0; i < 4; i++) outb[(q0 + i) * 192 + j] = acc[i];
    }
    __syncthreads();

    // attn_proj + add shortcut into g_y
    {
        int q0 = z * 4;
        float acc[4];
        float bb = apb[c];
#pragma unroll
        for (int i = 0; i < 4; i++) acc[i] = bb;
        for (int j0 = 0; j0 < 192; j0 += 4) {
            float w0 = apw[(j0 + 0) * 192 + c], w1 = apw[(j0 + 1) * 192 + c];
            float w2 = apw[(j0 + 2) * 192 + c], w3 = apw[(j0 + 3) * 192 + c];
#pragma unroll
            for (int i = 0; i < 4; i++) {
                float4 ov = *(const float4*)(outb + (q0 + i) * 192 + j0);
                acc[i] = fmaf(ov.x, w0, acc[i]); acc[i] = fmaf(ov.y, w1, acc[i]);
                acc[i] = fmaf(ov.z, w2, acc[i]); acc[i] = fmaf(ov.w, w3, acc[i]);
            }
        }
#pragma unroll
        for (int i = 0; i < 4; i++) {
            int qi = q0 + i;
            int gr = wi * 4 + (qi >> 2), gc = wj * 4 + (qi & 3);
            size_t yi = (((size_t)b * 128 + gr) * 128 + gc) * 192 + c;
            g_y[yi] += acc[i];
        }
    }
}

// ---------------------------------------------------------------------------
// K4: LN2 + MLP (gelu exact) + residual.  768 threads, 32 tokens/block.
// smem: syn[32*192] | hbuf[32*768]  = 120 KB
// ---------------------------------------------------------------------------
__global__ __launch_bounds__(768, 1) void k_mlp(const float* __restrict__ g2,
                                                const float* __restrict__ b2,
                                                const float* __restrict__ w1,
                                                const float* __restrict__ b1,
                                                const float* __restrict__ w2,
                                                const float* __restrict__ bo,
                                                float* __restrict__ out) {
    extern __shared__ float sm[];
    float* syn  = sm;          // 32 x 192
    float* hbuf = sm + 6144;   // 32 x 768
    int tid = threadIdx.x;
    int tok0 = blockIdx.x * 32;
    int warp = tid >> 5, lane = tid & 31;

    for (int t = warp; t < 32; t += 24) {
        const float* yp = g_y + (size_t)(tok0 + t) * 192;
        float v[6];
        float s = 0.f;
#pragma unroll
        for (int i = 0; i < 6; i++) { v[i] = yp[lane + 32 * i]; s += v[i]; }
#pragma unroll
        for (int o = 16; o; o >>= 1) s += __shfl_xor_sync(0xffffffffu, s, o);
        float m = s * (1.0f / 192.0f);
        float q = 0.f;
#pragma unroll
        for (int i = 0; i < 6; i++) { v[i] -= m; q += v[i] * v[i]; }
#pragma unroll
        for (int o = 16; o; o >>= 1) q += __shfl_xor_sync(0xffffffffu, q, o);
        float inv = rsqrtf(q * (1.0f / 192.0f) + 1e-6f);
#pragma unroll
        for (int i = 0; i < 6; i++)
            syn[t * 192 + lane + 32 * i] = v[i] * inv * g2[lane + 32 * i] + b2[lane + 32 * i];
    }
    __syncthreads();

    // hidden = gelu(syn @ w1 + b1): one pass, c = tid covers all 768 cols
    {
        int c = tid;
        float acc[32];
#pragma unroll
        for (int t = 0; t < 32; t++) acc[t] = 0.f;
        for (int k0 = 0; k0 < 192; k0 += 4) {
            float w_0 = w1[(k0 + 0) * 768 + c], w_1 = w1[(k0 + 1) * 768 + c];
            float w_2 = w1[(k0 + 2) * 768 + c], w_3 = w1[(k0 + 3) * 768 + c];
#pragma unroll
            for (int t = 0; t < 32; t++) {
                float4 xv = *(const float4*)(syn + t * 192 + k0);
                acc[t] = fmaf(xv.x, w_0, acc[t]); acc[t] = fmaf(xv.y, w_1, acc[t]);
                acc[t] = fmaf(xv.z, w_2, acc[t]); acc[t] = fmaf(xv.w, w_3, acc[t]);
            }
        }
        float bias = b1[c];
#pragma unroll
        for (int t = 0; t < 32; t++) {
            float u = acc[t] + bias;
            hbuf[t * 768 + c] = 0.5f * u * (1.0f + erff(u * 0.70710678118f));
        }
    }
    __syncthreads();

    // out = y + hbuf @ w2 + bo : z in 0..3, 8 tokens per thread
    {
        int c = tid % 192, z = tid / 192;
        int t0 = z * 8;
        float acc[8];
        float bias = bo[c];
#pragma unroll
        for (int t = 0; t < 8; t++) acc[t] = bias;
        for (int k0 = 0; k0 < 768; k0 += 4) {
            float w_0 = w2[(k0 + 0) * 192 + c], w_1 = w2[(k0 + 1) * 192 + c];
            float w_2 = w2[(k0 + 2) * 192 + c], w_3 = w2[(k0 + 3) * 192 + c];
#pragma unroll
            for (int t = 0; t < 8; t++) {
                float4 hv = *(const float4*)(hbuf + (t0 + t) * 768 + k0);
                acc[t] = fmaf(hv.x, w_0, acc[t]); acc[t] = fmaf(hv.y, w_1, acc[t]);
                acc[t] = fmaf(hv.z, w_2, acc[t]); acc[t] = fmaf(hv.w, w_3, acc[t]);
            }
        }
#pragma unroll
        for (int t = 0; t < 8; t++) {
            size_t idx = (size_t)(tok0 + t0 + t) * 192 + c;
            out[idx] = g_y[idx] + acc[t];
        }
    }
}

// ---------------------------------------------------------------------------
extern "C" void kernel_launch(void* const* d_in, const int* in_sizes, int n_in,
                              void* d_out, int out_size) {
    const float* x    = (const float*)d_in[0];
    const float* n1g  = (const float*)d_in[1];
    const float* n1b  = (const float*)d_in[2];
    const float* pw   = (const float*)d_in[3];
    const float* pb   = (const float*)d_in[4];
    const float* qkvw = (const float*)d_in[5];
    const float* qkvb = (const float*)d_in[6];
    const float* apw  = (const float*)d_in[7];
    const float* apb  = (const float*)d_in[8];
    const float* n2g  = (const float*)d_in[9];
    const float* n2b  = (const float*)d_in[10];
    const float* w1   = (const float*)d_in[11];
    const float* b1   = (const float*)d_in[12];
    const float* w2   = (const float*)d_in[13];
    const float* b2   = (const float*)d_in[14];
    float* out = (float*)d_out;

    cudaFuncSetAttribute(k_attn, cudaFuncAttributeMaxDynamicSharedMemorySize, 209472);
    cudaFuncSetAttribute(k_mlp,  cudaFuncAttributeMaxDynamicSharedMemorySize, 122880);

    k_ln1 <<<32768, 256>>>(x, n1g, n1b);
    k_short<<<8192, 384>>>(pw, pb);
    k_attn <<<4096, 768, 209472>>>(qkvw, qkvb, apw, apb);
    k_mlp  <<<2048, 768, 122880>>>(n2g, n2b, w1, b1, w2, b2, out);
}

// round 6
// speedup vs baseline: 1.3957x; 1.2077x over previous
#include <cuda_runtime.h>
#include <math.h>

#define BB   4
#define DOUT 192
#define HID  768
#define RS   193   // padded row stride for k/v/q smem buffers

__device__ float g_xn[(size_t)BB * 256 * 256 * 96];   // LN1 output
__device__ float g_y [(size_t)BB * 128 * 128 * 192];  // shortcut + attn out

// ---------------------------------------------------------------------------
// K1: LayerNorm over DIM=96, one warp per token
// ---------------------------------------------------------------------------
__global__ __launch_bounds__(256) void k_ln1(const float* __restrict__ x,
                                             const float* __restrict__ gma,
                                             const float* __restrict__ bta) {
    int wid  = blockIdx.x * (blockDim.x >> 5) + (threadIdx.x >> 5);
    int lane = threadIdx.x & 31;
    const float* xp = x + (size_t)wid * 96;
    float v0 = xp[lane], v1 = xp[lane + 32], v2 = xp[lane + 64];
    float s = v0 + v1 + v2;
#pragma unroll
    for (int o = 16; o; o >>= 1) s += __shfl_xor_sync(0xffffffffu, s, o);
    float m = s * (1.0f / 96.0f);
    float d0 = v0 - m, d1 = v1 - m, d2 = v2 - m;
    float q = d0 * d0 + d1 * d1 + d2 * d2;
#pragma unroll
    for (int o = 16; o; o >>= 1) q += __shfl_xor_sync(0xffffffffu, q, o);
    float inv = rsqrtf(q * (1.0f / 96.0f) + 1e-6f);
    float* op = g_xn + (size_t)wid * 96;
    op[lane]      = d0 * inv * gma[lane]      + bta[lane];
    op[lane + 32] = d1 * inv * gma[lane + 32] + bta[lane + 32];
    op[lane + 64] = d2 * inv * gma[lane + 64] + bta[lane + 64];
}

// ---------------------------------------------------------------------------
// K2: shortcut = maxpool2x2(xn @ proj_w + proj_b).  384 thr, 32 tokens/blk.
// thread tile: 4 tokens x 4 cols (outer product)
// ---------------------------------------------------------------------------
__global__ __launch_bounds__(384) void k_short(const float* __restrict__ pw,
                                               const float* __restrict__ pb) {
    __shared__ float sx[32 * 96];
    __shared__ float pr[32 * 192];
    int blk = blockIdx.x;
    int pwg = blk & 15, ph = (blk >> 4) & 127, b = blk >> 11;
    int tid = threadIdx.x;

    for (int i = tid; i < 32 * 24; i += 384) {
        int t = i / 24, kq = i - t * 24;
        int gr = 2 * ph + (t >> 4);
        int gc = (pwg << 4) + (t & 15);
        ((float4*)sx)[i] =
            *(const float4*)(g_xn + (((size_t)b * 256 + gr) * 256 + gc) * 96 + kq * 4);
    }
    __syncthreads();

    int c4 = (tid % 48) * 4, tg = tid / 48;       // tg 0..7 -> 4 tokens
    int t0 = tg * 4;
    float4 acc[4];
    float4 bb = *(const float4*)(pb + c4);
#pragma unroll
    for (int i = 0; i < 4; i++) acc[i] = bb;
    for (int k0 = 0; k0 < 96; k0 += 4) {
        float4 w0 = *(const float4*)(pw + (k0 + 0) * 192 + c4);
        float4 w1 = *(const float4*)(pw + (k0 + 1) * 192 + c4);
        float4 w2 = *(const float4*)(pw + (k0 + 2) * 192 + c4);
        float4 w3 = *(const float4*)(pw + (k0 + 3) * 192 + c4);
#pragma unroll
        for (int i = 0; i < 4; i++) {
            float4 a = *(const float4*)(sx + (t0 + i) * 96 + k0);
            acc[i].x = fmaf(a.x, w0.x, acc[i].x); acc[i].y = fmaf(a.x, w0.y, acc[i].y);
            acc[i].z = fmaf(a.x, w0.z, acc[i].z); acc[i].w = fmaf(a.x, w0.w, acc[i].w);
            acc[i].x = fmaf(a.y, w1.x, acc[i].x); acc[i].y = fmaf(a.y, w1.y, acc[i].y);
            acc[i].z = fmaf(a.y, w1.z, acc[i].z); acc[i].w = fmaf(a.y, w1.w, acc[i].w);
            acc[i].x = fmaf(a.z, w2.x, acc[i].x); acc[i].y = fmaf(a.z, w2.y, acc[i].y);
            acc[i].z = fmaf(a.z, w2.z, acc[i].z); acc[i].w = fmaf(a.z, w2.w, acc[i].w);
            acc[i].x = fmaf(a.w, w3.x, acc[i].x); acc[i].y = fmaf(a.w, w3.y, acc[i].y);
            acc[i].z = fmaf(a.w, w3.z, acc[i].z); acc[i].w = fmaf(a.w, w3.w, acc[i].w);
        }
    }
#pragma unroll
    for (int i = 0; i < 4; i++) *(float4*)(pr + (t0 + i) * 192 + c4) = acc[i];
    __syncthreads();

    for (int i = tid; i < 8 * 192; i += 384) {
        int p = i / 192, cc = i - p * 192;
        float m = fmaxf(fmaxf(pr[(2 * p) * 192 + cc], pr[(2 * p + 1) * 192 + cc]),
                        fmaxf(pr[(16 + 2 * p) * 192 + cc], pr[(17 + 2 * p) * 192 + cc]));
        g_y[(((size_t)b * 128 + ph) * 128 + (pwg * 8 + p)) * 192 + cc] = m;
    }
}

// ---------------------------------------------------------------------------
// K3: fused window attention.  768 threads / 8x8 window.
// qkv GEMM thread tile: 4 tokens x 4 cols.
// ---------------------------------------------------------------------------
__global__ __launch_bounds__(768, 1) void k_attn(const float* __restrict__ qkvw,
                                                 const float* __restrict__ qkvb,
                                                 const float* __restrict__ apw,
                                                 const float* __restrict__ apb) {
    extern __shared__ float sm[];
    float* sx    = sm;            // 64 x 96
    float* wst   = sm + 6144;     // 96 x 192 staged weights
    float* kb    = sm + 24576;    // 64 x RS
    float* vb    = sm + 36928;    // 64 x RS
    float* qb    = sm + 49280;    // 16 x RS
    float* probs = wst;           // 48 x 65
    float* outb  = wst + 3120;    // 16 x 192

    int wj = blockIdx.x & 31, wi = (blockIdx.x >> 5) & 31, b = blockIdx.x >> 10;
    int tid = threadIdx.x;

    for (int i = tid; i < 64 * 24; i += 768) {
        int t = i / 24, kq = i - t * 24;
        int gr = wi * 8 + (t >> 3), gc = wj * 8 + (t & 7);
        ((float4*)sx)[i] =
            *(const float4*)(g_xn + (((size_t)b * 256 + gr) * 256 + gc) * 96 + kq * 4);
    }

    int c4 = (tid % 48) * 4, tg = tid / 48;   // tg 0..15 -> 4 tokens each
    int t0 = tg * 4;

    // qkv GEMMs: part 0 = Q (into kb temp, then pooled), 1 = K, 2 = V
    for (int part = 0; part < 3; part++) {
        __syncthreads();
        for (int i = tid; i < 96 * 48; i += 768) {
            int k = i / 48, cq = i - k * 48;
            ((float4*)wst)[k * 48 + cq] =
                *(const float4*)(qkvw + (size_t)k * 576 + part * 192 + cq * 4);
        }
        __syncthreads();
        float* dst = (part == 2) ? vb : kb;
        float4 acc[4];
        float4 bb = *(const float4*)(qkvb + part * 192 + c4);
#pragma unroll
        for (int i = 0; i < 4; i++) acc[i] = bb;
        for (int k0 = 0; k0 < 96; k0 += 4) {
            float4 w0 = *(const float4*)(wst + (k0 + 0) * 192 + c4);
            float4 w1 = *(const float4*)(wst + (k0 + 1) * 192 + c4);
            float4 w2 = *(const float4*)(wst + (k0 + 2) * 192 + c4);
            float4 w3 = *(const float4*)(wst + (k0 + 3) * 192 + c4);
#pragma unroll
            for (int i = 0; i < 4; i++) {
                float4 a = *(const float4*)(sx + (t0 + i) * 96 + k0);
                acc[i].x = fmaf(a.x, w0.x, acc[i].x); acc[i].y = fmaf(a.x, w0.y, acc[i].y);
                acc[i].z = fmaf(a.x, w0.z, acc[i].z); acc[i].w = fmaf(a.x, w0.w, acc[i].w);
                acc[i].x = fmaf(a.y, w1.x, acc[i].x); acc[i].y = fmaf(a.y, w1.y, acc[i].y);
                acc[i].z = fmaf(a.y, w1.z, acc[i].z); acc[i].w = fmaf(a.y, w1.w, acc[i].w);
                acc[i].x = fmaf(a.z, w2.x, acc[i].x); acc[i].y = fmaf(a.z, w2.y, acc[i].y);
                acc[i].z = fmaf(a.z, w2.z, acc[i].z); acc[i].w = fmaf(a.z, w2.w, acc[i].w);
                acc[i].x = fmaf(a.w, w3.x, acc[i].x); acc[i].y = fmaf(a.w, w3.y, acc[i].y);
                acc[i].z = fmaf(a.w, w3.z, acc[i].z); acc[i].w = fmaf(a.w, w3.w, acc[i].w);
            }
        }
#pragma unroll
        for (int i = 0; i < 4; i++) {
            float* dp = dst + (t0 + i) * RS + c4;
            dp[0] = acc[i].x; dp[1] = acc[i].y; dp[2] = acc[i].z; dp[3] = acc[i].w;
        }
        if (part == 0) {
            __syncthreads();
            for (int i = tid; i < 16 * 192; i += 768) {
                int qi = i / 192, cc = i - qi * 192;
                int prw = qi >> 2, pcl = qi & 3;
                int t00 = (2 * prw) * 8 + 2 * pcl;
                float m = fmaxf(fmaxf(kb[t00 * RS + cc], kb[(t00 + 1) * RS + cc]),
                                fmaxf(kb[(t00 + 8) * RS + cc], kb[(t00 + 9) * RS + cc]));
                qb[qi * RS + cc] = m * 0.125f;
            }
        }
    }
    __syncthreads();

    // scores
    {
        int hk = tid % 192;
        int ki = hk & 63, h = hk >> 6;
        int z = tid / 192;
        int q0 = z * 4;
        float acc[4];
#pragma unroll
        for (int i = 0; i < 4; i++) acc[i] = 0.f;
        const float* kpt = kb + ki * RS + h * 64;
        const float* qpt = qb + q0 * RS + h * 64;
        for (int d = 0; d < 64; d++) {
            float kv = kpt[d];
#pragma unroll
            for (int i = 0; i < 4; i++) acc[i] = fmaf(qpt[i * RS + d], kv, acc[i]);
        }
#pragma unroll
        for (int i = 0; i < 4; i++) probs[(h * 16 + q0 + i) * 65 + ki] = acc[i];
    }
    __syncthreads();

    // softmax over ki (48 rows)
    if (tid < 48) {
        float* row = probs + tid * 65;
        float mx = -1e30f;
        for (int i = 0; i < 64; i++) mx = fmaxf(mx, row[i]);
        float s = 0.f;
        for (int i = 0; i < 64; i++) { float e = __expf(row[i] - mx); row[i] = e; s += e; }
        float r = 1.0f / s;
        for (int i = 0; i < 64; i++) row[i] *= r;
    }
    __syncthreads();

    // out = probs @ V
    {
        int j = tid % 192;
        int h = j >> 6;
        int z = tid / 192;
        int q0 = z * 4;
        float acc[4];
#pragma unroll
        for (int i = 0; i < 4; i++) acc[i] = 0.f;
        for (int ki = 0; ki < 64; ki++) {
            float vv = vb[ki * RS + j];
#pragma unroll
            for (int i = 0; i < 4; i++)
                acc[i] = fmaf(probs[(h * 16 + q0 + i) * 65 + ki], vv, acc[i]);
        }
#pragma unroll
        for (int i = 0; i < 4; i++) outb[(q0 + i) * 192 + j] = acc[i];
    }
    __syncthreads();

    // attn_proj + add shortcut into g_y.  thread: 1 token (tg) x 4 cols (c4)
    {
        int qi = tg;  // 16 tokens
        float4 acc = *(const float4*)(apb + c4);
        const float* op = outb + qi * 192;
        for (int j0 = 0; j0 < 192; j0 += 4) {
            float4 w0 = *(const float4*)(apw + (j0 + 0) * 192 + c4);
            float4 w1 = *(const float4*)(apw + (j0 + 1) * 192 + c4);
            float4 w2 = *(const float4*)(apw + (j0 + 2) * 192 + c4);
            float4 w3 = *(const float4*)(apw + (j0 + 3) * 192 + c4);
            float4 a = *(const float4*)(op + j0);
            acc.x = fmaf(a.x, w0.x, acc.x); acc.y = fmaf(a.x, w0.y, acc.y);
            acc.z = fmaf(a.x, w0.z, acc.z); acc.w = fmaf(a.x, w0.w, acc.w);
            acc.x = fmaf(a.y, w1.x, acc.x); acc.y = fmaf(a.y, w1.y, acc.y);
            acc.z = fmaf(a.y, w1.z, acc.z); acc.w = fmaf(a.y, w1.w, acc.w);
            acc.x = fmaf(a.z, w2.x, acc.x); acc.y = fmaf(a.z, w2.y, acc.y);
            acc.z = fmaf(a.z, w2.z, acc.z); acc.w = fmaf(a.z, w2.w, acc.w);
            acc.x = fmaf(a.w, w3.x, acc.x); acc.y = fmaf(a.w, w3.y, acc.y);
            acc.z = fmaf(a.w, w3.z, acc.z); acc.w = fmaf(a.w, w3.w, acc.w);
        }
        int gr = wi * 4 + (qi >> 2), gc = wj * 4 + (qi & 3);
        float* yp = g_y + (((size_t)b * 128 + gr) * 128 + gc) * 192 + c4;
        float4 yv = *(float4*)yp;
        yv.x += acc.x; yv.y += acc.y; yv.z += acc.z; yv.w += acc.w;
        *(float4*)yp = yv;
    }
}

// ---------------------------------------------------------------------------
// K4: LN2 + MLP + residual.  768 threads, 32 tokens/block.
// GEMM1 tile: 8 tok x 4 cols.  GEMM2 tile: 2 tok x 4 cols.
// ---------------------------------------------------------------------------
__global__ __launch_bounds__(768, 1) void k_mlp(const float* __restrict__ g2,
                                                const float* __restrict__ b2,
                                                const float* __restrict__ w1,
                                                const float* __restrict__ b1,
                                                const float* __restrict__ w2,
                                                const float* __restrict__ bo,
                                                float* __restrict__ out) {
    extern __shared__ float sm[];
    float* syn  = sm;          // 32 x 192
    float* hbuf = sm + 6144;   // 32 x 768
    int tid = threadIdx.x;
    int tok0 = blockIdx.x * 32;
    int warp = tid >> 5, lane = tid & 31;

    for (int t = warp; t < 32; t += 24) {
        const float* yp = g_y + (size_t)(tok0 + t) * 192;
        float v[6];
        float s = 0.f;
#pragma unroll
        for (int i = 0; i < 6; i++) { v[i] = yp[lane + 32 * i]; s += v[i]; }
#pragma unroll
        for (int o = 16; o; o >>= 1) s += __shfl_xor_sync(0xffffffffu, s, o);
        float m = s * (1.0f / 192.0f);
        float q = 0.f;
#pragma unroll
        for (int i = 0; i < 6; i++) { v[i] -= m; q += v[i] * v[i]; }
#pragma unroll
        for (int o = 16; o; o >>= 1) q += __shfl_xor_sync(0xffffffffu, q, o);
        float inv = rsqrtf(q * (1.0f / 192.0f) + 1e-6f);
#pragma unroll
        for (int i = 0; i < 6; i++)
            syn[t * 192 + lane + 32 * i] = v[i] * inv * g2[lane + 32 * i] + b2[lane + 32 * i];
    }
    __syncthreads();

    // hidden = gelu(syn @ w1 + b1): thread tile 8 tokens x 4 cols
    {
        int c4 = (tid % 192) * 4, tg = tid / 192;   // tg 0..3 -> 8 tokens
        int t0 = tg * 8;
        float4 acc[8];
        float4 bb = *(const float4*)(b1 + c4);
#pragma unroll
        for (int t = 0; t < 8; t++) acc[t] = bb;
        for (int k0 = 0; k0 < 192; k0 += 4) {
            float4 w_0 = *(const float4*)(w1 + (size_t)(k0 + 0) * 768 + c4);
            float4 w_1 = *(const float4*)(w1 + (size_t)(k0 + 1) * 768 + c4);
            float4 w_2 = *(const float4*)(w1 + (size_t)(k0 + 2) * 768 + c4);
            float4 w_3 = *(const float4*)(w1 + (size_t)(k0 + 3) * 768 + c4);
#pragma unroll
            for (int t = 0; t < 8; t++) {
                float4 a = *(const float4*)(syn + (t0 + t) * 192 + k0);
                acc[t].x = fmaf(a.x, w_0.x, acc[t].x); acc[t].y = fmaf(a.x, w_0.y, acc[t].y);
                acc[t].z = fmaf(a.x, w_0.z, acc[t].z); acc[t].w = fmaf(a.x, w_0.w, acc[t].w);
                acc[t].x = fmaf(a.y, w_1.x, acc[t].x); acc[t].y = fmaf(a.y, w_1.y, acc[t].y);
                acc[t].z = fmaf(a.y, w_1.z, acc[t].z); acc[t].w = fmaf(a.y, w_1.w, acc[t].w);
                acc[t].x = fmaf(a.z, w_2.x, acc[t].x); acc[t].y = fmaf(a.z, w_2.y, acc[t].y);
                acc[t].z = fmaf(a.z, w_2.z, acc[t].z); acc[t].w = fmaf(a.z, w_2.w, acc[t].w);
                acc[t].x = fmaf(a.w, w_3.x, acc[t].x); acc[t].y = fmaf(a.w, w_3.y, acc[t].y);
                acc[t].z = fmaf(a.w, w_3.z, acc[t].z); acc[t].w = fmaf(a.w, w_3.w, acc[t].w);
            }
        }
#pragma unroll
        for (int t = 0; t < 8; t++) {
            float4 u = acc[t];
            u.x = 0.5f * u.x * (1.0f + erff(u.x * 0.70710678118f));
            u.y = 0.5f * u.y * (1.0f + erff(u.y * 0.70710678118f));
            u.z = 0.5f * u.z * (1.0f + erff(u.z * 0.70710678118f));
            u.w = 0.5f * u.w * (1.0f + erff(u.w * 0.70710678118f));
            *(float4*)(hbuf + (t0 + t) * 768 + c4) = u;
        }
    }
    __syncthreads();

    // out = y + hbuf @ w2 + bo: thread tile 2 tokens x 4 cols
    {
        int c4 = (tid % 48) * 4, tg = tid / 48;    // tg 0..15 -> 2 tokens
        int t0 = tg * 2;
        float4 acc[2];
        float4 bb = *(const float4*)(bo + c4);
        acc[0] = bb; acc[1] = bb;
        for (int k0 = 0; k0 < 768; k0 += 4) {
            float4 w_0 = *(const float4*)(w2 + (size_t)(k0 + 0) * 192 + c4);
            float4 w_1 = *(const float4*)(w2 + (size_t)(k0 + 1) * 192 + c4);
            float4 w_2 = *(const float4*)(w2 + (size_t)(k0 + 2) * 192 + c4);
            float4 w_3 = *(const float4*)(w2 + (size_t)(k0 + 3) * 192 + c4);
#pragma unroll
            for (int t = 0; t < 2; t++) {
                float4 a = *(const float4*)(hbuf + (t0 + t) * 768 + k0);
                acc[t].x = fmaf(a.x, w_0.x, acc[t].x); acc[t].y = fmaf(a.x, w_0.y, acc[t].y);
                acc[t].z = fmaf(a.x, w_0.z, acc[t].z); acc[t].w = fmaf(a.x, w_0.w, acc[t].w);
                acc[t].x = fmaf(a.y, w_1.x, acc[t].x); acc[t].y = fmaf(a.y, w_1.y, acc[t].y);
                acc[t].z = fmaf(a.y, w_1.z, acc[t].z); acc[t].w = fmaf(a.y, w_1.w, acc[t].w);
                acc[t].x = fmaf(a.z, w_2.x, acc[t].x); acc[t].y = fmaf(a.z, w_2.y, acc[t].y);
                acc[t].z = fmaf(a.z, w_2.z, acc[t].z); acc[t].w = fmaf(a.z, w_2.w, acc[t].w);
                acc[t].x = fmaf(a.w, w_3.x, acc[t].x); acc[t].y = fmaf(a.w, w_3.y, acc[t].y);
                acc[t].z = fmaf(a.w, w_3.z, acc[t].z); acc[t].w = fmaf(a.w, w_3.w, acc[t].w);
            }
        }
#pragma unroll
        for (int t = 0; t < 2; t++) {
            size_t idx = (size_t)(tok0 + t0 + t) * 192 + c4;
            float4 yv = *(const float4*)(g_y + idx);
            yv.x += acc[t].x; yv.y += acc[t].y; yv.z += acc[t].z; yv.w += acc[t].w;
            *(float4*)(out + idx) = yv;
        }
    }
}

// ---------------------------------------------------------------------------
extern "C" void kernel_launch(void* const* d_in, const int* in_sizes, int n_in,
                              void* d_out, int out_size) {
    const float* x    = (const float*)d_in[0];
    const float* n1g  = (const float*)d_in[1];
    const float* n1b  = (const float*)d_in[2];
    const float* pw   = (const float*)d_in[3];
    const float* pb   = (const float*)d_in[4];
    const float* qkvw = (const float*)d_in[5];
    const float* qkvb = (const float*)d_in[6];
    const float* apw  = (const float*)d_in[7];
    const float* apb  = (const float*)d_in[8];
    const float* n2g  = (const float*)d_in[9];
    const float* n2b  = (const float*)d_in[10];
    const float* w1   = (const float*)d_in[11];
    const float* b1   = (const float*)d_in[12];
    const float* w2   = (const float*)d_in[13];
    const float* b2   = (const float*)d_in[14];
    float* out = (float*)d_out;

    cudaFuncSetAttribute(k_attn, cudaFuncAttributeMaxDynamicSharedMemorySize, 209472);
    cudaFuncSetAttribute(k_mlp,  cudaFuncAttributeMaxDynamicSharedMemorySize, 122880);

    k_ln1 <<<32768, 256>>>(x, n1g, n1b);
    k_short<<<8192, 384>>>(pw, pb);
    k_attn <<<4096, 768, 209472>>>(qkvw, qkvb, apw, apb);
    k_mlp  <<<2048, 768, 122880>>>(n2g, n2b, w1, b1, w2, b2, out);
}

// round 8
// speedup vs baseline: 1.6661x; 1.1937x over previous
#include <cuda_runtime.h>
#include <math.h>

#define BB   4
#define RS   193    // padded row stride for k/v/q smem buffers
#define SYN_S 196   // syn row stride  (196 mod 32 = 4 -> conflict-free mma A-frag loads)
#define HB_S  772   // hbuf row stride (772 mod 32 = 4)

__device__ float g_xn[(size_t)BB * 256 * 256 * 96];   // LN1 output
__device__ float g_y [(size_t)BB * 128 * 128 * 192];  // shortcut + attn out

// ---- tf32 mma helpers -----------------------------------------------------
__device__ __forceinline__ unsigned f2tf(float f) {
    unsigned u;
    asm("cvt.rna.tf32.f32 %0, %1;" : "=r"(u) : "f"(f));
    return u;
}
__device__ __forceinline__ void mma_tf32(float c[4],
                                         unsigned a0, unsigned a1, unsigned a2, unsigned a3,
                                         unsigned b0, unsigned b1) {
    asm("mma.sync.aligned.m16n8k8.row.col.f32.tf32.tf32.f32 "
        "{%0,%1,%2,%3},{%4,%5,%6,%7},{%8,%9},{%0,%1,%2,%3};"
        : "+f"(c[0]), "+f"(c[1]), "+f"(c[2]), "+f"(c[3])
        : "r"(a0), "r"(a1), "r"(a2), "r"(a3), "r"(b0), "r"(b1));
}

// ---------------------------------------------------------------------------
// K1: LayerNorm over DIM=96, one warp per token
// ---------------------------------------------------------------------------
__global__ __launch_bounds__(256) void k_ln1(const float* __restrict__ x,
                                             const float* __restrict__ gma,
                                             const float* __restrict__ bta) {
    int wid  = blockIdx.x * (blockDim.x >> 5) + (threadIdx.x >> 5);
    int lane = threadIdx.x & 31;
    const float* xp = x + (size_t)wid * 96;
    float v0 = xp[lane], v1 = xp[lane + 32], v2 = xp[lane + 64];
    float s = v0 + v1 + v2;
#pragma unroll
    for (int o = 16; o; o >>= 1) s += __shfl_xor_sync(0xffffffffu, s, o);
    float m = s * (1.0f / 96.0f);
    float d0 = v0 - m, d1 = v1 - m, d2 = v2 - m;
    float q = d0 * d0 + d1 * d1 + d2 * d2;
#pragma unroll
    for (int o = 16; o; o >>= 1) q += __shfl_xor_sync(0xffffffffu, q, o);
    float inv = rsqrtf(q * (1.0f / 96.0f) + 1e-6f);
    float* op = g_xn + (size_t)wid * 96;
    op[lane]      = d0 * inv * gma[lane]      + bta[lane];
    op[lane + 32] = d1 * inv * gma[lane + 32] + bta[lane + 32];
    op[lane + 64] = d2 * inv * gma[lane + 64] + bta[lane + 64];
}

// ---------------------------------------------------------------------------
// K2: shortcut = maxpool2x2(xn @ proj_w + proj_b).  384 thr, 32 tokens/blk.
// ---------------------------------------------------------------------------
__global__ __launch_bounds__(384) void k_short(const float* __restrict__ pw,
                                               const float* __restrict__ pb) {
    __shared__ float sx[32 * 96];
    __shared__ float pr[32 * 192];
    int blk = blockIdx.x;
    int pwg = blk & 15, ph = (blk >> 4) & 127, b = blk >> 11;
    int tid = threadIdx.x;

    for (int i = tid; i < 32 * 24; i += 384) {
        int t = i / 24, kq = i - t * 24;
        int gr = 2 * ph + (t >> 4);
        int gc = (pwg << 4) + (t & 15);
        ((float4*)sx)[i] =
            *(const float4*)(g_xn + (((size_t)b * 256 + gr) * 256 + gc) * 96 + kq * 4);
    }
    __syncthreads();

    int c4 = (tid % 48) * 4, tg = tid / 48;
    int t0 = tg * 4;
    float4 acc[4];
    float4 bb = *(const float4*)(pb + c4);
#pragma unroll
    for (int i = 0; i < 4; i++) acc[i] = bb;
    for (int k0 = 0; k0 < 96; k0 += 4) {
        float4 w0 = *(const float4*)(pw + (k0 + 0) * 192 + c4);
        float4 w1 = *(const float4*)(pw + (k0 + 1) * 192 + c4);
        float4 w2 = *(const float4*)(pw + (k0 + 2) * 192 + c4);
        float4 w3 = *(const float4*)(pw + (k0 + 3) * 192 + c4);
#pragma unroll
        for (int i = 0; i < 4; i++) {
            float4 a = *(const float4*)(sx + (t0 + i) * 96 + k0);
            acc[i].x = fmaf(a.x, w0.x, acc[i].x); acc[i].y = fmaf(a.x, w0.y, acc[i].y);
            acc[i].z = fmaf(a.x, w0.z, acc[i].z); acc[i].w = fmaf(a.x, w0.w, acc[i].w);
            acc[i].x = fmaf(a.y, w1.x, acc[i].x); acc[i].y = fmaf(a.y, w1.y, acc[i].y);
            acc[i].z = fmaf(a.y, w1.z, acc[i].z); acc[i].w = fmaf(a.y, w1.w, acc[i].w);
            acc[i].x = fmaf(a.z, w2.x, acc[i].x); acc[i].y = fmaf(a.z, w2.y, acc[i].y);
            acc[i].z = fmaf(a.z, w2.z, acc[i].z); acc[i].w = fmaf(a.z, w2.w, acc[i].w);
            acc[i].x = fmaf(a.w, w3.x, acc[i].x); acc[i].y = fmaf(a.w, w3.y, acc[i].y);
            acc[i].z = fmaf(a.w, w3.z, acc[i].z); acc[i].w = fmaf(a.w, w3.w, acc[i].w);
        }
    }
#pragma unroll
    for (int i = 0; i < 4; i++) *(float4*)(pr + (t0 + i) * 192 + c4) = acc[i];
    __syncthreads();

    for (int i = tid; i < 8 * 192; i += 384) {
        int p = i / 192, cc = i - p * 192;
        float m = fmaxf(fmaxf(pr[(2 * p) * 192 + cc], pr[(2 * p + 1) * 192 + cc]),
                        fmaxf(pr[(16 + 2 * p) * 192 + cc], pr[(17 + 2 * p) * 192 + cc]));
        g_y[(((size_t)b * 128 + ph) * 128 + (pwg * 8 + p)) * 192 + cc] = m;
    }
}

// ---------------------------------------------------------------------------
// K3: fused window attention.  768 threads / 8x8 window.  (unchanged, fp32)
// ---------------------------------------------------------------------------
__global__ __launch_bounds__(768, 1) void k_attn(const float* __restrict__ qkvw,
                                                 const float* __restrict__ qkvb,
                                                 const float* __restrict__ apw,
                                                 const float* __restrict__ apb) {
    extern __shared__ float sm[];
    float* sx    = sm;            // 64 x 96
    float* wst   = sm + 6144;     // 96 x 192 staged weights
    float* kb    = sm + 24576;    // 64 x RS
    float* vb    = sm + 36928;    // 64 x RS
    float* qb    = sm + 49280;    // 16 x RS
    float* probs = wst;           // 48 x 65
    float* outb  = wst + 3120;    // 16 x 192

    int wj = blockIdx.x & 31, wi = (blockIdx.x >> 5) & 31, b = blockIdx.x >> 10;
    int tid = threadIdx.x;

    for (int i = tid; i < 64 * 24; i += 768) {
        int t = i / 24, kq = i - t * 24;
        int gr = wi * 8 + (t >> 3), gc = wj * 8 + (t & 7);
        ((float4*)sx)[i] =
            *(const float4*)(g_xn + (((size_t)b * 256 + gr) * 256 + gc) * 96 + kq * 4);
    }

    int c4 = (tid % 48) * 4, tg = tid / 48;
    int t0 = tg * 4;

    for (int part = 0; part < 3; part++) {
        __syncthreads();
        for (int i = tid; i < 96 * 48; i += 768) {
            int k = i / 48, cq = i - k * 48;
            ((float4*)wst)[k * 48 + cq] =
                *(const float4*)(qkvw + (size_t)k * 576 + part * 192 + cq * 4);
        }
        __syncthreads();
        float* dst = (part == 2) ? vb : kb;
        float4 acc[4];
        float4 bb = *(const float4*)(qkvb + part * 192 + c4);
#pragma unroll
        for (int i = 0; i < 4; i++) acc[i] = bb;
        for (int k0 = 0; k0 < 96; k0 += 4) {
            float4 w0 = *(const float4*)(wst + (k0 + 0) * 192 + c4);
            float4 w1 = *(const float4*)(wst + (k0 + 1) * 192 + c4);
            float4 w2 = *(const float4*)(wst + (k0 + 2) * 192 + c4);
            float4 w3 = *(const float4*)(wst + (k0 + 3) * 192 + c4);
#pragma unroll
            for (int i = 0; i < 4; i++) {
                float4 a = *(const float4*)(sx + (t0 + i) * 96 + k0);
                acc[i].x = fmaf(a.x, w0.x, acc[i].x); acc[i].y = fmaf(a.x, w0.y, acc[i].y);
                acc[i].z = fmaf(a.x, w0.z, acc[i].z); acc[i].w = fmaf(a.x, w0.w, acc[i].w);
                acc[i].x = fmaf(a.y, w1.x, acc[i].x); acc[i].y = fmaf(a.y, w1.y, acc[i].y);
                acc[i].z = fmaf(a.y, w1.z, acc[i].z); acc[i].w = fmaf(a.y, w1.w, acc[i].w);
                acc[i].x = fmaf(a.z, w2.x, acc[i].x); acc[i].y = fmaf(a.z, w2.y, acc[i].y);
                acc[i].z = fmaf(a.z, w2.z, acc[i].z); acc[i].w = fmaf(a.z, w2.w, acc[i].w);
                acc[i].x = fmaf(a.w, w3.x, acc[i].x); acc[i].y = fmaf(a.w, w3.y, acc[i].y);
                acc[i].z = fmaf(a.w, w3.z, acc[i].z); acc[i].w = fmaf(a.w, w3.w, acc[i].w);
            }
        }
#pragma unroll
        for (int i = 0; i < 4; i++) {
            float* dp = dst + (t0 + i) * RS + c4;
            dp[0] = acc[i].x; dp[1] = acc[i].y; dp[2] = acc[i].z; dp[3] = acc[i].w;
        }
        if (part == 0) {
            __syncthreads();
            for (int i = tid; i < 16 * 192; i += 768) {
                int qi = i / 192, cc = i - qi * 192;
                int prw = qi >> 2, pcl = qi & 3;
                int t00 = (2 * prw) * 8 + 2 * pcl;
                float m = fmaxf(fmaxf(kb[t00 * RS + cc], kb[(t00 + 1) * RS + cc]),
                                fmaxf(kb[(t00 + 8) * RS + cc], kb[(t00 + 9) * RS + cc]));
                qb[qi * RS + cc] = m * 0.125f;
            }
        }
    }
    __syncthreads();

    {
        int hk = tid % 192;
        int ki = hk & 63, h = hk >> 6;
        int z = tid / 192;
        int q0 = z * 4;
        float acc[4];
#pragma unroll
        for (int i = 0; i < 4; i++) acc[i] = 0.f;
        const float* kpt = kb + ki * RS + h * 64;
        const float* qpt = qb + q0 * RS + h * 64;
        for (int d = 0; d < 64; d++) {
            float kv = kpt[d];
#pragma unroll
            for (int i = 0; i < 4; i++) acc[i] = fmaf(qpt[i * RS + d], kv, acc[i]);
        }
#pragma unroll
        for (int i = 0; i < 4; i++) probs[(h * 16 + q0 + i) * 65 + ki] = acc[i];
    }
    __syncthreads();

    if (tid < 48) {
        float* row = probs + tid * 65;
        float mx = -1e30f;
        for (int i = 0; i < 64; i++) mx = fmaxf(mx, row[i]);
        float s = 0.f;
        for (int i = 0; i < 64; i++) { float e = __expf(row[i] - mx); row[i] = e; s += e; }
        float r = 1.0f / s;
        for (int i = 0; i < 64; i++) row[i] *= r;
    }
    __syncthreads();

    {
        int j = tid % 192;
        int h = j >> 6;
        int z = tid / 192;
        int q0 = z * 4;
        float acc[4];
#pragma unroll
        for (int i = 0; i < 4; i++) acc[i] = 0.f;
        for (int ki = 0; ki < 64; ki++) {
            float vv = vb[ki * RS + j];
#pragma unroll
            for (int i = 0; i < 4; i++)
                acc[i] = fmaf(probs[(h * 16 + q0 + i) * 65 + ki], vv, acc[i]);
        }
#pragma unroll
        for (int i = 0; i < 4; i++) outb[(q0 + i) * 192 + j] = acc[i];
    }
    __syncthreads();

    {
        int qi = tg;
        float4 acc = *(const float4*)(apb + c4);
        const float* op = outb + qi * 192;
        for (int j0 = 0; j0 < 192; j0 += 4) {
            float4 w0 = *(const float4*)(apw + (j0 + 0) * 192 + c4);
            float4 w1 = *(const float4*)(apw + (j0 + 1) * 192 + c4);
            float4 w2 = *(const float4*)(apw + (j0 + 2) * 192 + c4);
            float4 w3 = *(const float4*)(apw + (j0 + 3) * 192 + c4);
            float4 a = *(const float4*)(op + j0);
            acc.x = fmaf(a.x, w0.x, acc.x); acc.y = fmaf(a.x, w0.y, acc.y);
            acc.z = fmaf(a.x, w0.z, acc.z); acc.w = fmaf(a.x, w0.w, acc.w);
            acc.x = fmaf(a.y, w1.x, acc.x); acc.y = fmaf(a.y, w1.y, acc.y);
            acc.z = fmaf(a.y, w1.z, acc.z); acc.w = fmaf(a.y, w1.w, acc.w);
            acc.x = fmaf(a.z, w2.x, acc.x); acc.y = fmaf(a.z, w2.y, acc.y);
            acc.z = fmaf(a.z, w2.z, acc.z); acc.w = fmaf(a.z, w2.w, acc.w);
            acc.x = fmaf(a.w, w3.x, acc.x); acc.y = fmaf(a.w, w3.y, acc.y);
            acc.z = fmaf(a.w, w3.z, acc.z); acc.w = fmaf(a.w, w3.w, acc.w);
        }
        int gr = wi * 4 + (qi >> 2), gc = wj * 4 + (qi & 3);
        float* yp = g_y + (((size_t)b * 128 + gr) * 128 + gc) * 192 + c4;
        float4 yv = *(float4*)yp;
        yv.x += acc.x; yv.y += acc.y; yv.z += acc.z; yv.w += acc.w;
        *(float4*)yp = yv;
    }
}

// ---------------------------------------------------------------------------
// K4: LN2 + MLP + residual via tf32 tensor-core mma.  768 threads, 32 tok/blk.
// smem: syn[32*196] | hbuf[32*772]  = 121 KB
// GEMM1: C[32x768], warps = 2 rowblocks x 12 colranges (8 n-tiles of m16n8k8)
// GEMM2: C[32x192], warps = 2 rowblocks x 12 colranges (2 n-tiles)
// ---------------------------------------------------------------------------
__global__ __launch_bounds__(768, 1) void k_mlp(const float* __restrict__ g2,
                                                const float* __restrict__ b2,
                                                const float* __restrict__ w1,
                                                const float* __restrict__ b1,
                                                const float* __restrict__ w2,
                                                const float* __restrict__ bo,
                                                float* __restrict__ out) {
    extern __shared__ float sm[];
    float* syn  = sm;               // 32 x SYN_S
    float* hbuf = sm + 32 * SYN_S;  // 32 x HB_S
    int tid = threadIdx.x;
    int tok0 = blockIdx.x * 32;
    int warp = tid >> 5, lane = tid & 31;
    int gid = lane >> 2, tig = lane & 3;

    // --- LN2 into syn ---
    for (int t = warp; t < 32; t += 24) {
        const float* yp = g_y + (size_t)(tok0 + t) * 192;
        float v[6];
        float s = 0.f;
#pragma unroll
        for (int i = 0; i < 6; i++) { v[i] = yp[lane + 32 * i]; s += v[i]; }
#pragma unroll
        for (int o = 16; o; o >>= 1) s += __shfl_xor_sync(0xffffffffu, s, o);
        float m = s * (1.0f / 192.0f);
        float q = 0.f;
#pragma unroll
        for (int i = 0; i < 6; i++) { v[i] -= m; q += v[i] * v[i]; }
#pragma unroll
        for (int o = 16; o; o >>= 1) q += __shfl_xor_sync(0xffffffffu, q, o);
        float inv = rsqrtf(q * (1.0f / 192.0f) + 1e-6f);
#pragma unroll
        for (int i = 0; i < 6; i++)
            syn[t * SYN_S + lane + 32 * i] = v[i] * inv * g2[lane + 32 * i] + b2[lane + 32 * i];
    }
    __syncthreads();

    // --- GEMM1: hidden = gelu(syn @ w1 + b1) ---
    {
        int rb = warp & 1;
        int nb = (warp >> 1) * 64;
        float c[8][4];
#pragma unroll
        for (int j = 0; j < 8; j++)
#pragma unroll
            for (int i = 0; i < 4; i++) c[j][i] = 0.f;

        const float* ar0 = syn + (rb * 16 + gid) * SYN_S + tig;
        const float* ar1 = ar0 + 8 * SYN_S;
        const float* wb  = w1 + nb + gid;
#pragma unroll 4
        for (int kk = 0; kk < 24; kk++) {
            int k0 = kk * 8;
            unsigned a0 = f2tf(ar0[k0]),     a1 = f2tf(ar1[k0]);
            unsigned a2 = f2tf(ar0[k0 + 4]), a3 = f2tf(ar1[k0 + 4]);
            const float* wr0 = wb + (size_t)(k0 + tig) * 768;
            const float* wr1 = wr0 + 4 * 768;
#pragma unroll
            for (int j = 0; j < 8; j++) {
                unsigned b0 = f2tf(wr0[j * 8]);
                unsigned b1 = f2tf(wr1[j * 8]);
                mma_tf32(c[j], a0, a1, a2, a3, b0, b1);
            }
        }
        int r0 = rb * 16 + gid, r1 = r0 + 8;
#pragma unroll
        for (int j = 0; j < 8; j++) {
            int col0 = nb + j * 8 + tig * 2;
            float bb0 = b1[col0], bb1 = b1[col0 + 1];
            float u;
            u = c[j][0] + bb0; hbuf[r0 * HB_S + col0]     = 0.5f * u * (1.0f + erff(u * 0.70710678118f));
            u = c[j][1] + bb1; hbuf[r0 * HB_S + col0 + 1] = 0.5f * u * (1.0f + erff(u * 0.70710678118f));
            u = c[j][2] + bb0; hbuf[r1 * HB_S + col0]     = 0.5f * u * (1.0f + erff(u * 0.70710678118f));
            u = c[j][3] + bb1; hbuf[r1 * HB_S + col0 + 1] = 0.5f * u * (1.0f + erff(u * 0.70710678118f));
        }
    }
    __syncthreads();

    // --- GEMM2: out = y + hbuf @ w2 + bo ---
    {
        int rb = warp & 1;
        int nb = (warp >> 1) * 16;
        float c[2][4];
#pragma unroll
        for (int j = 0; j < 2; j++)
#pragma unroll
            for (int i = 0; i < 4; i++) c[j][i] = 0.f;

        const float* ar0 = hbuf + (rb * 16 + gid) * HB_S + tig;
        const float* ar1 = ar0 + 8 * HB_S;
        const float* wb  = w2 + nb + gid;
#pragma unroll 4
        for (int kk = 0; kk < 96; kk++) {
            int k0 = kk * 8;
            unsigned a0 = f2tf(ar0[k0]),     a1 = f2tf(ar1[k0]);
            unsigned a2 = f2tf(ar0[k0 + 4]), a3 = f2tf(ar1[k0 + 4]);
            const float* wr0 = wb + (size_t)(k0 + tig) * 192;
            const float* wr1 = wr0 + 4 * 192;
#pragma unroll
            for (int j = 0; j < 2; j++) {
                unsigned b0 = f2tf(wr0[j * 8]);
                unsigned b1 = f2tf(wr1[j * 8]);
                mma_tf32(c[j], a0, a1, a2, a3, b0, b1);
            }
        }
        int r0 = rb * 16 + gid, r1 = r0 + 8;
#pragma unroll
        for (int j = 0; j < 2; j++) {
            int col0 = nb + j * 8 + tig * 2;
            float bb0 = bo[col0], bb1 = bo[col0 + 1];
            size_t i00 = (size_t)(tok0 + r0) * 192 + col0;
            size_t i10 = (size_t)(tok0 + r1) * 192 + col0;
            out[i00]     = g_y[i00]     + c[j][0] + bb0;
            out[i00 + 1] = g_y[i00 + 1] + c[j][1] + bb1;
            out[i10]     = g_y[i10]     + c[j][2] + bb0;
            out[i10 + 1] = g_y[i10 + 1] + c[j][3] + bb1;
        }
    }
}

// ---------------------------------------------------------------------------
extern "C" void kernel_launch(void* const* d_in, const int* in_sizes, int n_in,
                              void* d_out, int out_size) {
    const float* x    = (const float*)d_in[0];
    const float* n1g  = (const float*)d_in[1];
    const float* n1b  = (const float*)d_in[2];
    const float* pw   = (const float*)d_in[3];
    const float* pb   = (const float*)d_in[4];
    const float* qkvw = (const float*)d_in[5];
    const float* qkvb = (const float*)d_in[6];
    const float* apw  = (const float*)d_in[7];
    const float* apb  = (const float*)d_in[8];
    const float* n2g  = (const float*)d_in[9];
    const float* n2b  = (const float*)d_in[10];
    const float* w1   = (const float*)d_in[11];
    const float* b1   = (const float*)d_in[12];
    const float* w2   = (const float*)d_in[13];
    const float* b2   = (const float*)d_in[14];
    float* out = (float*)d_out;

    const int smem_mlp = (32 * SYN_S + 32 * HB_S) * 4;   // 123,904 B

    cudaFuncSetAttribute(k_attn, cudaFuncAttributeMaxDynamicSharedMemorySize, 209472);
    cudaFuncSetAttribute(k_mlp,  cudaFuncAttributeMaxDynamicSharedMemorySize, smem_mlp);

    k_ln1 <<<32768, 256>>>(x, n1g, n1b);
    k_short<<<8192, 384>>>(pw, pb);
    k_attn <<<4096, 768, 209472>>>(qkvw, qkvb, apw, apb);
    k_mlp  <<<2048, 768, smem_mlp>>>(n2g, n2b, w1, b1, w2, b2, out);
}

// round 15
// speedup vs baseline: 1.9846x; 1.1912x over previous
#include <cuda_runtime.h>
#include <math.h>

#define BB   4
#define RS   193    // padded row stride for k/v/q smem buffers
#define SYN_S 196   // syn row stride  (196 mod 32 = 4 -> conflict-free mma A-frag loads)
#define HB_S  772   // hbuf row stride (772 mod 32 = 4)

__device__ float g_xn[(size_t)BB * 256 * 256 * 96];   // LN1 output
__device__ float g_y [(size_t)BB * 128 * 128 * 192];  // shortcut + attn out

// Pre-packed tf32 B-fragments for k_mlp (filled by k_prep each launch)
__device__ uint4 g_w1q[12 * 24 * 4 * 32];   // GEMM1: [cr][kk][jp][lane]
__device__ uint4 g_w2q[12 * 96 * 32];       // GEMM2: [cr][kk][lane]

// ---- tf32 mma helpers -----------------------------------------------------
__device__ __forceinline__ unsigned f2tf(float f) {
    unsigned u;
    asm("cvt.rna.tf32.f32 %0, %1;" : "=r"(u) : "f"(f));
    return u;
}
__device__ __forceinline__ void mma_tf32(float c[4],
                                         unsigned a0, unsigned a1, unsigned a2, unsigned a3,
                                         unsigned b0, unsigned b1) {
    asm("mma.sync.aligned.m16n8k8.row.col.f32.tf32.tf32.f32 "
        "{%0,%1,%2,%3},{%4,%5,%6,%7},{%8,%9},{%0,%1,%2,%3};"
        : "+f"(c[0]), "+f"(c[1]), "+f"(c[2]), "+f"(c[3])
        : "r"(a0), "r"(a1), "r"(a2), "r"(a3), "r"(b0), "r"(b1));
}

// ---------------------------------------------------------------------------
// K0: pack w1/w2 into tf32 mma-fragment order (one-time per launch, tiny)
// ---------------------------------------------------------------------------
__global__ __launch_bounds__(256) void k_prep(const float* __restrict__ w1,
                                              const float* __restrict__ w2) {
    int tid = blockIdx.x * 256 + threadIdx.x;   // 73728 total
    if (tid < 36864) {
        int lane = tid & 31; int rem = tid >> 5;
        int jp = rem & 3; rem >>= 2;
        int kk = rem % 24, cr = rem / 24;
        int gid = lane >> 2, tig = lane & 3;
        int r0 = kk * 8 + tig, r1 = r0 + 4;
        int c0 = cr * 64 + (2 * jp) * 8 + gid, c1 = c0 + 8;
        uint4 v;
        v.x = f2tf(w1[r0 * 768 + c0]); v.y = f2tf(w1[r1 * 768 + c0]);
        v.z = f2tf(w1[r0 * 768 + c1]); v.w = f2tf(w1[r1 * 768 + c1]);
        g_w1q[tid] = v;
    } else {
        int t = tid - 36864;
        int lane = t & 31; int rem = t >> 5;
        int kk = rem % 96, cr = rem / 96;
        int gid = lane >> 2, tig = lane & 3;
        int r0 = kk * 8 + tig, r1 = r0 + 4;
        int c0 = cr * 16 + gid, c1 = c0 + 8;
        uint4 v;
        v.x = f2tf(w2[r0 * 192 + c0]); v.y = f2tf(w2[r1 * 192 + c0]);
        v.z = f2tf(w2[r0 * 192 + c1]); v.w = f2tf(w2[r1 * 192 + c1]);
        g_w2q[t] = v;
    }
}

// ---------------------------------------------------------------------------
// K1: LayerNorm over DIM=96, one warp per token
// ---------------------------------------------------------------------------
__global__ __launch_bounds__(256) void k_ln1(const float* __restrict__ x,
                                             const float* __restrict__ gma,
                                             const float* __restrict__ bta) {
    int wid  = blockIdx.x * (blockDim.x >> 5) + (threadIdx.x >> 5);
    int lane = threadIdx.x & 31;
    const float* xp = x + (size_t)wid * 96;
    float v0 = xp[lane], v1 = xp[lane + 32], v2 = xp[lane + 64];
    float s = v0 + v1 + v2;
#pragma unroll
    for (int o = 16; o; o >>= 1) s += __shfl_xor_sync(0xffffffffu, s, o);
    float m = s * (1.0f / 96.0f);
    float d0 = v0 - m, d1 = v1 - m, d2 = v2 - m;
    float q = d0 * d0 + d1 * d1 + d2 * d2;
#pragma unroll
    for (int o = 16; o; o >>= 1) q += __shfl_xor_sync(0xffffffffu, q, o);
    float inv = rsqrtf(q * (1.0f / 96.0f) + 1e-6f);
    float* op = g_xn + (size_t)wid * 96;
    op[lane]      = d0 * inv * gma[lane]      + bta[lane];
    op[lane + 32] = d1 * inv * gma[lane + 32] + bta[lane + 32];
    op[lane + 64] = d2 * inv * gma[lane + 64] + bta[lane + 64];
}

// ---------------------------------------------------------------------------
// K2: shortcut = maxpool2x2(xn @ proj_w + proj_b).  384 thr, 32 tokens/blk.
// ---------------------------------------------------------------------------
__global__ __launch_bounds__(384) void k_short(const float* __restrict__ pw,
                                               const float* __restrict__ pb) {
    __shared__ float sx[32 * 96];
    __shared__ float pr[32 * 192];
    int blk = blockIdx.x;
    int pwg = blk & 15, ph = (blk >> 4) & 127, b = blk >> 11;
    int tid = threadIdx.x;

    for (int i = tid; i < 32 * 24; i += 384) {
        int t = i / 24, kq = i - t * 24;
        int gr = 2 * ph + (t >> 4);
        int gc = (pwg << 4) + (t & 15);
        ((float4*)sx)[i] =
            *(const float4*)(g_xn + (((size_t)b * 256 + gr) * 256 + gc) * 96 + kq * 4);
    }
    __syncthreads();

    int c4 = (tid % 48) * 4, tg = tid / 48;
    int t0 = tg * 4;
    float4 acc[4];
    float4 bb = *(const float4*)(pb + c4);
#pragma unroll
    for (int i = 0; i < 4; i++) acc[i] = bb;
    for (int k0 = 0; k0 < 96; k0 += 4) {
        float4 w0 = *(const float4*)(pw + (k0 + 0) * 192 + c4);
        float4 w1 = *(const float4*)(pw + (k0 + 1) * 192 + c4);
        float4 w2 = *(const float4*)(pw + (k0 + 2) * 192 + c4);
        float4 w3 = *(const float4*)(pw + (k0 + 3) * 192 + c4);
#pragma unroll
        for (int i = 0; i < 4; i++) {
            float4 a = *(const float4*)(sx + (t0 + i) * 96 + k0);
            acc[i].x = fmaf(a.x, w0.x, acc[i].x); acc[i].y = fmaf(a.x, w0.y, acc[i].y);
            acc[i].z = fmaf(a.x, w0.z, acc[i].z); acc[i].w = fmaf(a.x, w0.w, acc[i].w);
            acc[i].x = fmaf(a.y, w1.x, acc[i].x); acc[i].y = fmaf(a.y, w1.y, acc[i].y);
            acc[i].z = fmaf(a.y, w1.z, acc[i].z); acc[i].w = fmaf(a.y, w1.w, acc[i].w);
            acc[i].x = fmaf(a.z, w2.x, acc[i].x); acc[i].y = fmaf(a.z, w2.y, acc[i].y);
            acc[i].z = fmaf(a.z, w2.z, acc[i].z); acc[i].w = fmaf(a.z, w2.w, acc[i].w);
            acc[i].x = fmaf(a.w, w3.x, acc[i].x); acc[i].y = fmaf(a.w, w3.y, acc[i].y);
            acc[i].z = fmaf(a.w, w3.z, acc[i].z); acc[i].w = fmaf(a.w, w3.w, acc[i].w);
        }
    }
#pragma unroll
    for (int i = 0; i < 4; i++) *(float4*)(pr + (t0 + i) * 192 + c4) = acc[i];
    __syncthreads();

    for (int i = tid; i < 8 * 192; i += 384) {
        int p = i / 192, cc = i - p * 192;
        float m = fmaxf(fmaxf(pr[(2 * p) * 192 + cc], pr[(2 * p + 1) * 192 + cc]),
                        fmaxf(pr[(16 + 2 * p) * 192 + cc], pr[(17 + 2 * p) * 192 + cc]));
        g_y[(((size_t)b * 128 + ph) * 128 + (pwg * 8 + p)) * 192 + cc] = m;
    }
}

// ---------------------------------------------------------------------------
// K3: fused window attention.  768 threads / 8x8 window.  (fp32)
// ---------------------------------------------------------------------------
__global__ __launch_bounds__(768, 1) void k_attn(const float* __restrict__ qkvw,
                                                 const float* __restrict__ qkvb,
                                                 const float* __restrict__ apw,
                                                 const float* __restrict__ apb) {
    extern __shared__ float sm[];
    float* sx    = sm;            // 64 x 96
    float* wst   = sm + 6144;     // 96 x 192 staged weights
    float* kb    = sm + 24576;    // 64 x RS
    float* vb    = sm + 36928;    // 64 x RS
    float* qb    = sm + 49280;    // 16 x RS
    float* probs = wst;           // 48 x 65
    float* outb  = wst + 3120;    // 16 x 192

    int wj = blockIdx.x & 31, wi = (blockIdx.x >> 5) & 31, b = blockIdx.x >> 10;
    int tid = threadIdx.x;

    for (int i = tid; i < 64 * 24; i += 768) {
        int t = i / 24, kq = i - t * 24;
        int gr = wi * 8 + (t >> 3), gc = wj * 8 + (t & 7);
        ((float4*)sx)[i] =
            *(const float4*)(g_xn + (((size_t)b * 256 + gr) * 256 + gc) * 96 + kq * 4);
    }

    int c4 = (tid % 48) * 4, tg = tid / 48;
    int t0 = tg * 4;

    for (int part = 0; part < 3; part++) {
        __syncthreads();
        for (int i = tid; i < 96 * 48; i += 768) {
            int k = i / 48, cq = i - k * 48;
            ((float4*)wst)[k * 48 + cq] =
                *(const float4*)(qkvw + (size_t)k * 576 + part * 192 + cq * 4);
        }
        __syncthreads();
        float* dst = (part == 2) ? vb : kb;
        float4 acc[4];
        float4 bb = *(const float4*)(qkvb + part * 192 + c4);
#pragma unroll
        for (int i = 0; i < 4; i++) acc[i] = bb;
        for (int k0 = 0; k0 < 96; k0 += 4) {
            float4 w0 = *(const float4*)(wst + (k0 + 0) * 192 + c4);
            float4 w1 = *(const float4*)(wst + (k0 + 1) * 192 + c4);
            float4 w2 = *(const float4*)(wst + (k0 + 2) * 192 + c4);
            float4 w3 = *(const float4*)(wst + (k0 + 3) * 192 + c4);
#pragma unroll
            for (int i = 0; i < 4; i++) {
                float4 a = *(const float4*)(sx + (t0 + i) * 96 + k0);
                acc[i].x = fmaf(a.x, w0.x, acc[i].x); acc[i].y = fmaf(a.x, w0.y, acc[i].y);
                acc[i].z = fmaf(a.x, w0.z, acc[i].z); acc[i].w = fmaf(a.x, w0.w, acc[i].w);
                acc[i].x = fmaf(a.y, w1.x, acc[i].x); acc[i].y = fmaf(a.y, w1.y, acc[i].y);
                acc[i].z = fmaf(a.y, w1.z, acc[i].z); acc[i].w = fmaf(a.y, w1.w, acc[i].w);
                acc[i].x = fmaf(a.z, w2.x, acc[i].x); acc[i].y = fmaf(a.z, w2.y, acc[i].y);
                acc[i].z = fmaf(a.z, w2.z, acc[i].z); acc[i].w = fmaf(a.z, w2.w, acc[i].w);
                acc[i].x = fmaf(a.w, w3.x, acc[i].x); acc[i].y = fmaf(a.w, w3.y, acc[i].y);
                acc[i].z = fmaf(a.w, w3.z, acc[i].z); acc[i].w = fmaf(a.w, w3.w, acc[i].w);
            }
        }
#pragma unroll
        for (int i = 0; i < 4; i++) {
            float* dp = dst + (t0 + i) * RS + c4;
            dp[0] = acc[i].x; dp[1] = acc[i].y; dp[2] = acc[i].z; dp[3] = acc[i].w;
        }
        if (part == 0) {
            __syncthreads();
            for (int i = tid; i < 16 * 192; i += 768) {
                int qi = i / 192, cc = i - qi * 192;
                int prw = qi >> 2, pcl = qi & 3;
                int t00 = (2 * prw) * 8 + 2 * pcl;
                float m = fmaxf(fmaxf(kb[t00 * RS + cc], kb[(t00 + 1) * RS + cc]),
                                fmaxf(kb[(t00 + 8) * RS + cc], kb[(t00 + 9) * RS + cc]));
                qb[qi * RS + cc] = m * 0.125f;
            }
        }
    }
    __syncthreads();

    {
        int hk = tid % 192;
        int ki = hk & 63, h = hk >> 6;
        int z = tid / 192;
        int q0 = z * 4;
        float acc[4];
#pragma unroll
        for (int i = 0; i < 4; i++) acc[i] = 0.f;
        const float* kpt = kb + ki * RS + h * 64;
        const float* qpt = qb + q0 * RS + h * 64;
        for (int d = 0; d < 64; d++) {
            float kv = kpt[d];
#pragma unroll
            for (int i = 0; i < 4; i++) acc[i] = fmaf(qpt[i * RS + d], kv, acc[i]);
        }
#pragma unroll
        for (int i = 0; i < 4; i++) probs[(h * 16 + q0 + i) * 65 + ki] = acc[i];
    }
    __syncthreads();

    if (tid < 48) {
        float* row = probs + tid * 65;
        float mx = -1e30f;
        for (int i = 0; i < 64; i++) mx = fmaxf(mx, row[i]);
        float s = 0.f;
        for (int i = 0; i < 64; i++) { float e = __expf(row[i] - mx); row[i] = e; s += e; }
        float r = 1.0f / s;
        for (int i = 0; i < 64; i++) row[i] *= r;
    }
    __syncthreads();

    {
        int j = tid % 192;
        int h = j >> 6;
        int z = tid / 192;
        int q0 = z * 4;
        float acc[4];
#pragma unroll
        for (int i = 0; i < 4; i++) acc[i] = 0.f;
        for (int ki = 0; ki < 64; ki++) {
            float vv = vb[ki * RS + j];
#pragma unroll
            for (int i = 0; i < 4; i++)
                acc[i] = fmaf(probs[(h * 16 + q0 + i) * 65 + ki], vv, acc[i]);
        }
#pragma unroll
        for (int i = 0; i < 4; i++) outb[(q0 + i) * 192 + j] = acc[i];
    }
    __syncthreads();

    {
        int qi = tg;
        float4 acc = *(const float4*)(apb + c4);
        const float* op = outb + qi * 192;
        for (int j0 = 0; j0 < 192; j0 += 4) {
            float4 w0 = *(const float4*)(apw + (j0 + 0) * 192 + c4);
            float4 w1 = *(const float4*)(apw + (j0 + 1) * 192 + c4);
            float4 w2 = *(const float4*)(apw + (j0 + 2) * 192 + c4);
            float4 w3 = *(const float4*)(apw + (j0 + 3) * 192 + c4);
            float4 a = *(const float4*)(op + j0);
            acc.x = fmaf(a.x, w0.x, acc.x); acc.y = fmaf(a.x, w0.y, acc.y);
            acc.z = fmaf(a.x, w0.z, acc.z); acc.w = fmaf(a.x, w0.w, acc.w);
            acc.x = fmaf(a.y, w1.x, acc.x); acc.y = fmaf(a.y, w1.y, acc.y);
            acc.z = fmaf(a.y, w1.z, acc.z); acc.w = fmaf(a.y, w1.w, acc.w);
            acc.x = fmaf(a.z, w2.x, acc.x); acc.y = fmaf(a.z, w2.y, acc.y);
            acc.z = fmaf(a.z, w2.z, acc.z); acc.w = fmaf(a.z, w2.w, acc.w);
            acc.x = fmaf(a.w, w3.x, acc.x); acc.y = fmaf(a.w, w3.y, acc.y);
            acc.z = fmaf(a.w, w3.z, acc.z); acc.w = fmaf(a.w, w3.w, acc.w);
        }
        int gr = wi * 4 + (qi >> 2), gc = wj * 4 + (qi & 3);
        float* yp = g_y + (((size_t)b * 128 + gr) * 128 + gc) * 192 + c4;
        float4 yv = *(float4*)yp;
        yv.x += acc.x; yv.y += acc.y; yv.z += acc.z; yv.w += acc.w;
        *(float4*)yp = yv;
    }
}

// ---------------------------------------------------------------------------
// K4: LN2 + MLP + residual, tf32 mma with pre-packed fragments.
// 768 threads, 32 tokens/block.  Inner loops are LDS/LDG.128/HMMA only.
// ---------------------------------------------------------------------------
__global__ __launch_bounds__(768, 1) void k_mlp(const float* __restrict__ g2,
                                                const float* __restrict__ b2,
                                                const float* __restrict__ b1,
                                                const float* __restrict__ bo,
                                                float* __restrict__ out) {
    extern __shared__ float sm[];
    unsigned* synb  = (unsigned*)sm;                // 32 x SYN_S (tf32 bits)
    unsigned* hbufb = (unsigned*)(sm + 32 * SYN_S); // 32 x HB_S  (tf32 bits)
    int tid = threadIdx.x;
    int tok0 = blockIdx.x * 32;
    int warp = tid >> 5, lane = tid & 31;
    int gid = lane >> 2, tig = lane & 3;

    // --- LN2 into synb (pre-converted tf32) ---
    for (int t = warp; t < 32; t += 24) {
        const float* yp = g_y + (size_t)(tok0 + t) * 192;
        float v[6];
        float s = 0.f;
#pragma unroll
        for (int i = 0; i < 6; i++) { v[i] = yp[lane + 32 * i]; s += v[i]; }
#pragma unroll
        for (int o = 16; o; o >>= 1) s += __shfl_xor_sync(0xffffffffu, s, o);
        float m = s * (1.0f / 192.0f);
        float q = 0.f;
#pragma unroll
        for (int i = 0; i < 6; i++) { v[i] -= m; q += v[i] * v[i]; }
#pragma unroll
        for (int o = 16; o; o >>= 1) q += __shfl_xor_sync(0xffffffffu, q, o);
        float inv = rsqrtf(q * (1.0f / 192.0f) + 1e-6f);
#pragma unroll
        for (int i = 0; i < 6; i++)
            synb[t * SYN_S + lane + 32 * i] =
                f2tf(v[i] * inv * g2[lane + 32 * i] + b2[lane + 32 * i]);
    }
    __syncthreads();

    // --- GEMM1: hidden = gelu(syn @ w1 + b1) ---
    {
        int rb = warp & 1;
        int cr = warp >> 1;             // 0..11
        int nb = cr * 64;
        float c[8][4];
#pragma unroll
        for (int j = 0; j < 8; j++)
#pragma unroll
            for (int i = 0; i < 4; i++) c[j][i] = 0.f;

        const unsigned* ar0 = synb + (rb * 16 + gid) * SYN_S + tig;
        const unsigned* ar1 = ar0 + 8 * SYN_S;
        const uint4* wq = g_w1q + (size_t)cr * 24 * 4 * 32 + lane;
#pragma unroll 4
        for (int kk = 0; kk < 24; kk++) {
            int k0 = kk * 8;
            unsigned a0 = ar0[k0],     a1 = ar1[k0];
            unsigned a2 = ar0[k0 + 4], a3 = ar1[k0 + 4];
            const uint4* wk = wq + kk * 4 * 32;
#pragma unroll
            for (int jp = 0; jp < 4; jp++) {
                uint4 bv = wk[jp * 32];
                mma_tf32(c[2 * jp],     a0, a1, a2, a3, bv.x, bv.y);
                mma_tf32(c[2 * jp + 1], a0, a1, a2, a3, bv.z, bv.w);
            }
        }
        int r0 = rb * 16 + gid, r1 = r0 + 8;
#pragma unroll
        for (int j = 0; j < 8; j++) {
            int col0 = nb + j * 8 + tig * 2;
            float bb0 = b1[col0], bb1 = b1[col0 + 1];
            float u;
            u = c[j][0] + bb0; hbufb[r0 * HB_S + col0]     = f2tf(0.5f * u * (1.0f + erff(u * 0.70710678118f)));
            u = c[j][1] + bb1; hbufb[r0 * HB_S + col0 + 1] = f2tf(0.5f * u * (1.0f + erff(u * 0.70710678118f)));
            u = c[j][2] + bb0; hbufb[r1 * HB_S + col0]     = f2tf(0.5f * u * (1.0f + erff(u * 0.70710678118f)));
            u = c[j][3] + bb1; hbufb[r1 * HB_S + col0 + 1] = f2tf(0.5f * u * (1.0f + erff(u * 0.70710678118f)));
        }
    }
    __syncthreads();

    // --- GEMM2: out = y + hbuf @ w2 + bo ---
    {
        int rb = warp & 1;
        int cr = warp >> 1;             // 0..11
        int nb = cr * 16;
        float c[2][4];
#pragma unroll
        for (int j = 0; j < 2; j++)
#pragma unroll
            for (int i = 0; i < 4; i++) c[j][i] = 0.f;

        const unsigned* ar0 = hbufb + (rb * 16 + gid) * HB_S + tig;
        const unsigned* ar1 = ar0 + 8 * HB_S;
        const uint4* wq = g_w2q + (size_t)cr * 96 * 32 + lane;
#pragma unroll 8
        for (int kk = 0; kk < 96; kk++) {
            int k0 = kk * 8;
            unsigned a0 = ar0[k0],     a1 = ar1[k0];
            unsigned a2 = ar0[k0 + 4], a3 = ar1[k0 + 4];
            uint4 bv = wq[kk * 32];
            mma_tf32(c[0], a0, a1, a2, a3, bv.x, bv.y);
            mma_tf32(c[1], a0, a1, a2, a3, bv.z, bv.w);
        }
        int r0 = rb * 16 + gid, r1 = r0 + 8;
#pragma unroll
        for (int j = 0; j < 2; j++) {
            int col0 = nb + j * 8 + tig * 2;
            float bb0 = bo[col0], bb1 = bo[col0 + 1];
            size_t i00 = (size_t)(tok0 + r0) * 192 + col0;
            size_t i10 = (size_t)(tok0 + r1) * 192 + col0;
            out[i00]     = g_y[i00]     + c[j][0] + bb0;
            out[i00 + 1] = g_y[i00 + 1] + c[j][1] + bb1;
            out[i10]     = g_y[i10]     + c[j][2] + bb0;
            out[i10 + 1] = g_y[i10 + 1] + c[j][3] + bb1;
        }
    }
}

// ---------------------------------------------------------------------------
extern "C" void kernel_launch(void* const* d_in, const int* in_sizes, int n_in,
                              void* d_out, int out_size) {
    const float* x    = (const float*)d_in[0];
    const float* n1g  = (const float*)d_in[1];
    const float* n1b  = (const float*)d_in[2];
    const float* pw   = (const float*)d_in[3];
    const float* pb   = (const float*)d_in[4];
    const float* qkvw = (const float*)d_in[5];
    const float* qkvb = (const float*)d_in[6];
    const float* apw  = (const float*)d_in[7];
    const float* apb  = (const float*)d_in[8];
    const float* n2g  = (const float*)d_in[9];
    const float* n2b  = (const float*)d_in[10];
    const float* w1   = (const float*)d_in[11];
    const float* b1   = (const float*)d_in[12];
    const float* w2   = (const float*)d_in[13];
    const float* b2   = (const float*)d_in[14];
    float* out = (float*)d_out;

    const int smem_mlp = (32 * SYN_S + 32 * HB_S) * 4;   // 123,904 B

    cudaFuncSetAttribute(k_attn, cudaFuncAttributeMaxDynamicSharedMemorySize, 209472);
    cudaFuncSetAttribute(k_mlp,  cudaFuncAttributeMaxDynamicSharedMemorySize, smem_mlp);

    k_prep <<<288, 256>>>(w1, w2);
    k_ln1 <<<32768, 256>>>(x, n1g, n1b);
    k_short<<<8192, 384>>>(pw, pb);
    k_attn <<<4096, 768, 209472>>>(qkvw, qkvb, apw, apb);
    k_mlp  <<<2048, 768, smem_mlp>>>(n2g, n2b, b1, b2, out);
}